// round 5
// baseline (speedup 1.0000x reference)
#include <cuda_runtime.h>
#include <cuda_bf16.h>
#include <math.h>

#define B_  2
#define S_  2048
#define E_  512
#define NH_ 4
#define DH_ 128
#define R_  (B_*S_)

// ------------------------- device scratch -------------------------
__device__ float g_xm  [R_*E_];
__device__ float g_zsil[R_*E_];
__device__ float g_xc  [R_*E_];
__device__ float g_q   [R_*E_];
__device__ float g_k   [R_*E_];
__device__ float g_v   [R_*E_];
__device__ float g_h   [R_*E_];
__device__ float g_hs  [R_*E_];
__device__ float g_Wt  [4*E_*E_];
__device__ float g_ig  [B_*NH_*S_];
__device__ float g_fg  [B_*NH_*S_];
__device__ float g_dkey[B_*NH_*S_];
__device__ float g_mrow[B_*NH_*S_];
__device__ float g_mexp[B_*NH_*S_];

// ---------------- conv weight transpose: Wt[tap][i][o] ----------------
__global__ void k_wt(const float* __restrict__ conv_w){
  int bi = blockIdx.x;              // tap*512 + i
  int tap = bi >> 9, i = bi & 511;
  int o = threadIdx.x;
  g_Wt[(size_t)bi*512 + o] = conv_w[((size_t)o*512 + i)*4 + tap];
}

// ---------------- up projection + split + silu(z) ----------------
__global__ __launch_bounds__(256) void k_up(const float* __restrict__ X,
                                            const float* __restrict__ Wup){
  __shared__ float As[16][128];
  __shared__ float Bs[16][65];
  int tid = threadIdx.x;
  int bm = blockIdx.y*128, bn = blockIdx.x*64;
  int lr = tid>>1, lc = (tid&1)*8;
  int bnn = tid>>2, bc4 = (tid&3)*4;
  int tx = tid&15, ty = tid>>4;
  float acc[8][4];
  #pragma unroll
  for(int i=0;i<8;i++){acc[i][0]=0;acc[i][1]=0;acc[i][2]=0;acc[i][3]=0;}
  for (int k0=0;k0<512;k0+=16){
    #pragma unroll
    for (int u=0;u<2;u++){
      float4 a = *(const float4*)&X[(size_t)(bm+lr)*512 + k0+lc+u*4];
      As[lc+u*4+0][lr]=a.x; As[lc+u*4+1][lr]=a.y; As[lc+u*4+2][lr]=a.z; As[lc+u*4+3][lr]=a.w;
    }
    {
      float4 b = *(const float4*)&Wup[(size_t)(bn+bnn)*512 + k0+bc4];
      Bs[bc4+0][bnn]=b.x; Bs[bc4+1][bnn]=b.y; Bs[bc4+2][bnn]=b.z; Bs[bc4+3][bnn]=b.w;
    }
    __syncthreads();
    #pragma unroll
    for(int kk=0;kk<16;kk++){
      float ra[8];
      *(float4*)ra     = *(const float4*)&As[kk][ty*8];
      *(float4*)(ra+4) = *(const float4*)&As[kk][ty*8+4];
      float b0=Bs[kk][tx*4+0], b1=Bs[kk][tx*4+1], b2=Bs[kk][tx*4+2], b3=Bs[kk][tx*4+3];
      #pragma unroll
      for(int i=0;i<8;i++){
        acc[i][0]+=ra[i]*b0; acc[i][1]+=ra[i]*b1; acc[i][2]+=ra[i]*b2; acc[i][3]+=ra[i]*b3;
      }
    }
    __syncthreads();
  }
  bool is_z = (bn >= 512);
  #pragma unroll
  for(int i=0;i<8;i++){
    int row = bm + ty*8 + i;
    int col = bn + tx*4;
    if (!is_z){
      *(float4*)&g_xm[(size_t)row*512 + col] =
        make_float4(acc[i][0],acc[i][1],acc[i][2],acc[i][3]);
    } else {
      float4 o;
      o.x = acc[i][0]/(1.f+__expf(-acc[i][0])); o.y = acc[i][1]/(1.f+__expf(-acc[i][1]));
      o.z = acc[i][2]/(1.f+__expf(-acc[i][2])); o.w = acc[i][3]/(1.f+__expf(-acc[i][3]));
      *(float4*)&g_zsil[(size_t)row*512 + (col-512)] = o;
    }
  }
}

// ---------------- causal conv1d as shifted GEMM + silu ----------------
__global__ __launch_bounds__(256) void k_conv(const float* __restrict__ convb){
  __shared__ float As[16][128];
  __shared__ float Bs[16][65];
  int tid = threadIdx.x;
  int bm = blockIdx.y*128, bn = blockIdx.x*64;
  int lr = tid>>1, lc = (tid&1)*8;
  int bcs = tid>>4;            // k 0..15
  int bn4 = (tid&15)*4;        // n
  int tx = tid&15, ty = tid>>4;
  float acc[8][4];
  #pragma unroll
  for(int i=0;i<8;i++){acc[i][0]=0;acc[i][1]=0;acc[i][2]=0;acc[i][3]=0;}
  int r = bm + lr;
  int s = r & (S_-1);
  for (int k0=0;k0<2048;k0+=16){
    int tap = k0>>9;
    int i0  = k0&511;
    bool ok = (s + tap - 3) >= 0;
    #pragma unroll
    for (int u=0;u<2;u++){
      float4 a = ok ? *(const float4*)&g_xm[(size_t)(r+tap-3)*512 + i0+lc+u*4]
                    : make_float4(0.f,0.f,0.f,0.f);
      As[lc+u*4+0][lr]=a.x; As[lc+u*4+1][lr]=a.y; As[lc+u*4+2][lr]=a.z; As[lc+u*4+3][lr]=a.w;
    }
    {
      float4 b = *(const float4*)&g_Wt[(size_t)(k0+bcs)*512 + bn + bn4];
      Bs[bcs][bn4+0]=b.x; Bs[bcs][bn4+1]=b.y; Bs[bcs][bn4+2]=b.z; Bs[bcs][bn4+3]=b.w;
    }
    __syncthreads();
    #pragma unroll
    for(int kk=0;kk<16;kk++){
      float ra[8];
      *(float4*)ra     = *(const float4*)&As[kk][ty*8];
      *(float4*)(ra+4) = *(const float4*)&As[kk][ty*8+4];
      float b0=Bs[kk][tx*4+0], b1=Bs[kk][tx*4+1], b2=Bs[kk][tx*4+2], b3=Bs[kk][tx*4+3];
      #pragma unroll
      for(int i=0;i<8;i++){
        acc[i][0]+=ra[i]*b0; acc[i][1]+=ra[i]*b1; acc[i][2]+=ra[i]*b2; acc[i][3]+=ra[i]*b3;
      }
    }
    __syncthreads();
  }
  #pragma unroll
  for(int i=0;i<8;i++){
    int row = bm + ty*8 + i;
    int col = bn + tx*4;
    float v0=acc[i][0]+convb[col+0], v1=acc[i][1]+convb[col+1];
    float v2=acc[i][2]+convb[col+2], v3=acc[i][3]+convb[col+3];
    float4 o;
    o.x = v0/(1.f+__expf(-v0)); o.y = v1/(1.f+__expf(-v1));
    o.z = v2/(1.f+__expf(-v2)); o.w = v3/(1.f+__expf(-v3));
    *(float4*)&g_xc[(size_t)row*512 + col] = o;
  }
}

// ---------------- headwise q/k/v ----------------
__global__ __launch_bounds__(256) void k_qkv(const float* __restrict__ Wq,
                                             const float* __restrict__ Wk,
                                             const float* __restrict__ Wv){
  __shared__ float As[16][128];
  __shared__ float Bs[16][65];
  int zz = blockIdx.z; int op = zz>>2; int h = zz&3;
  const float* A  = (op==2 ? g_xm : g_xc) + h*128;
  const float* Bp = (op==0 ? Wq : (op==1 ? Wk : Wv)) + (size_t)h*128*128;
  float* Cp = (op==0 ? g_q : (op==1 ? g_k : g_v)) + h*128;
  int tid = threadIdx.x;
  int bm = blockIdx.y*128, bn = blockIdx.x*64;
  int lr = tid>>1, lc = (tid&1)*8;
  int bnn = tid>>2, bc4 = (tid&3)*4;
  int tx = tid&15, ty = tid>>4;
  float acc[8][4];
  #pragma unroll
  for(int i=0;i<8;i++){acc[i][0]=0;acc[i][1]=0;acc[i][2]=0;acc[i][3]=0;}
  for (int k0=0;k0<128;k0+=16){
    #pragma unroll
    for (int u=0;u<2;u++){
      float4 a = *(const float4*)&A[(size_t)(bm+lr)*512 + k0+lc+u*4];
      As[lc+u*4+0][lr]=a.x; As[lc+u*4+1][lr]=a.y; As[lc+u*4+2][lr]=a.z; As[lc+u*4+3][lr]=a.w;
    }
    {
      float4 b = *(const float4*)&Bp[(size_t)(bn+bnn)*128 + k0+bc4];
      Bs[bc4+0][bnn]=b.x; Bs[bc4+1][bnn]=b.y; Bs[bc4+2][bnn]=b.z; Bs[bc4+3][bnn]=b.w;
    }
    __syncthreads();
    #pragma unroll
    for(int kk=0;kk<16;kk++){
      float ra[8];
      *(float4*)ra     = *(const float4*)&As[kk][ty*8];
      *(float4*)(ra+4) = *(const float4*)&As[kk][ty*8+4];
      float b0=Bs[kk][tx*4+0], b1=Bs[kk][tx*4+1], b2=Bs[kk][tx*4+2], b3=Bs[kk][tx*4+3];
      #pragma unroll
      for(int i=0;i<8;i++){
        acc[i][0]+=ra[i]*b0; acc[i][1]+=ra[i]*b1; acc[i][2]+=ra[i]*b2; acc[i][3]+=ra[i]*b3;
      }
    }
    __syncthreads();
  }
  #pragma unroll
  for(int i=0;i<8;i++){
    int row = bm + ty*8 + i;
    *(float4*)&Cp[(size_t)row*512 + bn + tx*4] =
      make_float4(acc[i][0],acc[i][1],acc[i][2],acc[i][3]);
  }
}

// ---------------- gate projections ----------------
__global__ void k_gates(const float* __restrict__ Wi, const float* __restrict__ bi,
                        const float* __restrict__ Wf, const float* __restrict__ bf){
  int r = blockIdx.x; int tid = threadIdx.x;     // 128 threads
  float pi[4]={0,0,0,0}, pf[4]={0,0,0,0};
  const float* qr = g_q + (size_t)r*512;
  const float* kr = g_k + (size_t)r*512;
  const float* vr = g_v + (size_t)r*512;
  for (int e=tid; e<512; e+=128){
    float a=qr[e], c=kr[e], d=vr[e];
    #pragma unroll
    for (int h=0;h<4;h++){
      const float* wih = Wi + h*1536; const float* wfh = Wf + h*1536;
      pi[h] += a*wih[e] + c*wih[512+e] + d*wih[1024+e];
      pf[h] += a*wfh[e] + c*wfh[512+e] + d*wfh[1024+e];
    }
  }
  __shared__ float red[8][128];
  #pragma unroll
  for (int h=0;h<4;h++){ red[h][tid]=pi[h]; red[4+h][tid]=pf[h]; }
  __syncthreads();
  for (int sft=64; sft>=1; sft>>=1){
    if (tid < sft){
      #pragma unroll
      for (int a=0;a<8;a++) red[a][tid]+=red[a][tid+sft];
    }
    __syncthreads();
  }
  if (tid < 4){
    int b = r>>11, s = r&2047;
    g_ig[((size_t)b*4+tid)*2048 + s] = red[tid][0]   + bi[tid];
    g_fg[((size_t)b*4+tid)*2048 + s] = red[4+tid][0] + bf[tid];
  }
}

// ---------------- per-(b,h) scan: dkey, prefix max, exp(-max_log_D) -------
__global__ void k_scan(){
  int bh = blockIdx.x; int t = threadIdx.x;      // 8 blocks x 256 thr x 8 elems
  const float* fg = g_fg + (size_t)bh*2048;
  const float* ig = g_ig + (size_t)bh*2048;
  double lcum[8]; double run = 0.0;
  #pragma unroll
  for (int u=0;u<8;u++){
    double x = (double)fg[t*8+u];
    double ls = (x < 0.0) ? (x - log1p(exp(x))) : (-log1p(exp(-x)));
    run += ls; lcum[u] = run;
  }
  __shared__ double sh[256];
  sh[t] = run; __syncthreads();
  for (int off=1; off<256; off<<=1){
    double cur = sh[t]; double oth = (t>=off)? sh[t-off] : 0.0;
    __syncthreads(); sh[t] = cur + oth; __syncthreads();
  }
  double base = (t>0)? sh[t-1] : 0.0;
  double dv[8], lf[8]; double runm = -1e300;
  #pragma unroll
  for (int u=0;u<8;u++){
    double lfc = base + lcum[u];
    lf[u] = lfc; dv[u] = (double)ig[t*8+u] - lfc;
    if (dv[u] > runm) runm = dv[u];
  }
  __syncthreads();
  sh[t] = runm; __syncthreads();
  for (int off=1; off<256; off<<=1){
    double cur = sh[t]; double oth = (t>=off)? sh[t-off] : -1e300;
    __syncthreads(); sh[t] = (cur>oth)?cur:oth; __syncthreads();
  }
  double basem = (t>0)? sh[t-1] : -1e300;
  double rm = basem;
  #pragma unroll
  for (int u=0;u<8;u++){
    if (dv[u] > rm) rm = dv[u];
    int j = bh*2048 + t*8 + u;
    g_dkey[j] = (float)dv[u];
    g_mrow[j] = (float)rm;
    g_mexp[j] = (float)exp(-(lf[u] + rm));
  }
}

// ---------------- flash-style causal mLSTM attention ----------------
// smem floats: Qs 64*132, KV 64*132, Ss 64*68, mr 64, dk 64, red 64*17, sinv 64
#define ATT_SMEM ((64*132 + 64*132 + 64*68 + 64 + 64 + 64*17 + 64)*4)
__global__ __launch_bounds__(256) void k_attn(){
  extern __shared__ float sm[];
  float* Qs  = sm;
  float* KV  = Qs + 64*132;
  float* Ss  = KV + 64*132;
  float* mr  = Ss + 64*68;
  float* dk  = mr + 64;
  float* red = dk + 64;
  float* sinv= red + 64*17;

  int bh = blockIdx.y; int b = bh>>2, h = bh&3;
  int it = (int)gridDim.x - 1 - (int)blockIdx.x;   // heavy tiles first
  int i0 = it*64;
  int tid = threadIdx.x;
  int tx = tid & 15, ty = tid >> 4;
  const float scale = 0.08838834764831845f;        // 1/sqrt(128)

  const float* qbase = g_q + ((size_t)(b*2048 + i0))*512 + h*128;
  for (int idx = tid; idx < 64*32; idx += 256){
    int row = idx >> 5, c4 = (idx & 31)*4;
    *(float4*)&Qs[row*132 + c4] = *(const float4*)&qbase[(size_t)row*512 + c4];
  }
  if (tid < 64) mr[tid] = g_mrow[bh*2048 + i0 + tid];

  float accB[4][8];
  #pragma unroll
  for (int i=0;i<4;i++){
    #pragma unroll
    for (int j=0;j<8;j++) accB[i][j]=0.f;
  }
  float psum[4] = {0.f,0.f,0.f,0.f};

  for (int j0 = 0; j0 <= i0; j0 += 64){
    __syncthreads();                                // KV free, Q ready
    const float* kbase = g_k + ((size_t)(b*2048 + j0))*512 + h*128;
    for (int idx = tid; idx < 64*32; idx += 256){
      int row = idx >> 5, c4 = (idx & 31)*4;
      *(float4*)&KV[row*132 + c4] = *(const float4*)&kbase[(size_t)row*512 + c4];
    }
    if (tid < 64) dk[tid] = g_dkey[bh*2048 + j0 + tid];
    __syncthreads();

    float a[4][4];
    #pragma unroll
    for (int u=0;u<4;u++){ a[u][0]=0;a[u][1]=0;a[u][2]=0;a[u][3]=0; }
    #pragma unroll 4
    for (int d=0; d<128; d+=4){
      float4 qf[4], kf[4];
      #pragma unroll
      for (int u=0;u<4;u++) qf[u] = *(float4*)&Qs[(ty*4+u)*132 + d];
      #pragma unroll
      for (int v=0;v<4;v++) kf[v] = *(float4*)&KV[(tx*4+v)*132 + d];
      #pragma unroll
      for (int u=0;u<4;u++){
        #pragma unroll
        for (int v=0;v<4;v++){
          a[u][v] += qf[u].x*kf[v].x + qf[u].y*kf[v].y + qf[u].z*kf[v].z + qf[u].w*kf[v].w;
        }
      }
    }
    bool diag = (j0 == i0);
    #pragma unroll
    for (int u=0;u<4;u++){
      int i = ty*4+u;
      #pragma unroll
      for (int v=0;v<4;v++){
        int j = tx*4+v;
        float s;
        if (diag && j > i) s = 0.f;
        else s = a[u][v]*scale*__expf(dk[j] - mr[i]);
        psum[u] += s;
        Ss[i*68 + j] = s;
      }
    }
    __syncthreads();

    const float* vbase = g_v + ((size_t)(b*2048 + j0))*512 + h*128;
    for (int idx = tid; idx < 64*32; idx += 256){
      int row = idx >> 5, c4 = (idx & 31)*4;
      *(float4*)&KV[row*132 + c4] = *(const float4*)&vbase[(size_t)row*512 + c4];
    }
    __syncthreads();

    #pragma unroll 2
    for (int j=0;j<64;j++){
      float sv[4];
      #pragma unroll
      for (int u=0;u<4;u++) sv[u] = Ss[(ty*4+u)*68 + j];
      float4 v0 = *(float4*)&KV[j*132 + tx*8];
      float4 v1 = *(float4*)&KV[j*132 + tx*8 + 4];
      #pragma unroll
      for (int u=0;u<4;u++){
        accB[u][0]+=sv[u]*v0.x; accB[u][1]+=sv[u]*v0.y; accB[u][2]+=sv[u]*v0.z; accB[u][3]+=sv[u]*v0.w;
        accB[u][4]+=sv[u]*v1.x; accB[u][5]+=sv[u]*v1.y; accB[u][6]+=sv[u]*v1.z; accB[u][7]+=sv[u]*v1.w;
      }
    }
  }

  #pragma unroll
  for (int u=0;u<4;u++) red[(ty*4+u)*17 + tx] = psum[u];
  __syncthreads();
  if (tid < 64){
    float s2 = 0.f;
    #pragma unroll
    for (int x2=0;x2<16;x2++) s2 += red[tid*17 + x2];
    float nrm = fmaxf(fabsf(s2), g_mexp[bh*2048 + i0 + tid]);
    sinv[tid] = 1.f/(nrm + 1e-6f);
  }
  __syncthreads();
  float* obase = g_h + ((size_t)(b*2048 + i0))*512 + h*128;
  #pragma unroll
  for (int u=0;u<4;u++){
    int i = ty*4+u; float iv = sinv[i];
    *(float4*)&obase[(size_t)i*512 + tx*8] =
      make_float4(accB[u][0]*iv, accB[u][1]*iv, accB[u][2]*iv, accB[u][3]*iv);
    *(float4*)&obase[(size_t)i*512 + tx*8 + 4] =
      make_float4(accB[u][4]*iv, accB[u][5]*iv, accB[u][6]*iv, accB[u][7]*iv);
  }
}

// ---------------- groupnorm + skip + z-gate ----------------
__global__ void k_norm(const float* __restrict__ skip){
  int r = blockIdx.x; int t = threadIdx.x;   // 128 threads
  float v[4];
  #pragma unroll
  for (int h=0;h<4;h++) v[h] = g_h[(size_t)r*512 + h*128 + t];
  __shared__ float rs[4][128], rq[4][128];
  #pragma unroll
  for (int h=0;h<4;h++){ rs[h][t]=v[h]; rq[h][t]=v[h]*v[h]; }
  __syncthreads();
  for (int sft=64; sft>=1; sft>>=1){
    if (t < sft){
      #pragma unroll
      for (int h=0;h<4;h++){ rs[h][t]+=rs[h][t+sft]; rq[h][t]+=rq[h][t+sft]; }
    }
    __syncthreads();
  }
  #pragma unroll
  for (int h=0;h<4;h++){
    float mean = rs[h][0]*(1.f/128.f);
    float var  = rq[h][0]*(1.f/128.f) - mean*mean;
    float hn = (v[h]-mean)*rsqrtf(var + 1e-5f);
    int e = h*128 + t;
    float hskip = hn + skip[e]*g_xc[(size_t)r*512 + e];
    g_hs[(size_t)r*512 + e] = hskip * g_zsil[(size_t)r*512 + e];
  }
}

// ---------------- down projection + bias ----------------
__global__ __launch_bounds__(256) void k_down(const float* __restrict__ Wd,
                                              const float* __restrict__ bd,
                                              float* __restrict__ out){
  __shared__ float As[16][128];
  __shared__ float Bs[16][65];
  int tid = threadIdx.x;
  int bm = blockIdx.y*128, bn = blockIdx.x*64;
  int lr = tid>>1, lc = (tid&1)*8;
  int bnn = tid>>2, bc4 = (tid&3)*4;
  int tx = tid&15, ty = tid>>4;
  float acc[8][4];
  #pragma unroll
  for(int i=0;i<8;i++){acc[i][0]=0;acc[i][1]=0;acc[i][2]=0;acc[i][3]=0;}
  for (int k0=0;k0<512;k0+=16){
    #pragma unroll
    for (int u=0;u<2;u++){
      float4 a = *(const float4*)&g_hs[(size_t)(bm+lr)*512 + k0+lc+u*4];
      As[lc+u*4+0][lr]=a.x; As[lc+u*4+1][lr]=a.y; As[lc+u*4+2][lr]=a.z; As[lc+u*4+3][lr]=a.w;
    }
    {
      float4 b = *(const float4*)&Wd[(size_t)(bn+bnn)*512 + k0+bc4];
      Bs[bc4+0][bnn]=b.x; Bs[bc4+1][bnn]=b.y; Bs[bc4+2][bnn]=b.z; Bs[bc4+3][bnn]=b.w;
    }
    __syncthreads();
    #pragma unroll
    for(int kk=0;kk<16;kk++){
      float ra[8];
      *(float4*)ra     = *(const float4*)&As[kk][ty*8];
      *(float4*)(ra+4) = *(const float4*)&As[kk][ty*8+4];
      float b0=Bs[kk][tx*4+0], b1=Bs[kk][tx*4+1], b2=Bs[kk][tx*4+2], b3=Bs[kk][tx*4+3];
      #pragma unroll
      for(int i=0;i<8;i++){
        acc[i][0]+=ra[i]*b0; acc[i][1]+=ra[i]*b1; acc[i][2]+=ra[i]*b2; acc[i][3]+=ra[i]*b3;
      }
    }
    __syncthreads();
  }
  #pragma unroll
  for(int i=0;i<8;i++){
    int row = bm + ty*8 + i;
    int col = bn + tx*4;
    *(float4*)&out[(size_t)row*512 + col] =
      make_float4(acc[i][0]+bd[col+0], acc[i][1]+bd[col+1],
                  acc[i][2]+bd[col+2], acc[i][3]+bd[col+3]);
  }
}

// ---------------- launch ----------------
extern "C" void kernel_launch(void* const* d_in, const int* in_sizes, int n_in,
                              void* d_out, int out_size){
  const float* x      = (const float*)d_in[0];
  const float* W_up   = (const float*)d_in[1];
  const float* Wq     = (const float*)d_in[2];
  const float* Wk     = (const float*)d_in[3];
  const float* Wv     = (const float*)d_in[4];
  const float* conv_w = (const float*)d_in[5];
  const float* conv_b = (const float*)d_in[6];
  const float* Wi     = (const float*)d_in[7];
  const float* bi     = (const float*)d_in[8];
  const float* Wf     = (const float*)d_in[9];
  const float* bf     = (const float*)d_in[10];
  const float* skip   = (const float*)d_in[11];
  const float* W_down = (const float*)d_in[12];
  const float* b_down = (const float*)d_in[13];
  float* out = (float*)d_out;

  static bool attr_set = false;
  if (!attr_set){
    cudaFuncSetAttribute(k_attn, cudaFuncAttributeMaxDynamicSharedMemorySize, ATT_SMEM);
    attr_set = true;
  }

  k_wt  <<<2048, 512>>>(conv_w);
  k_up  <<<dim3(16,32), 256>>>(x, W_up);
  k_conv<<<dim3(8,32), 256>>>(conv_b);
  k_qkv <<<dim3(2,32,12), 256>>>(Wq, Wk, Wv);
  k_gates<<<4096,128>>>(Wi, bi, Wf, bf);
  k_scan<<<8,256>>>();
  k_attn<<<dim3(32,8),256, ATT_SMEM>>>();
  k_norm<<<4096,128>>>(skip);
  k_down<<<dim3(8,32),256>>>(W_down, b_down, out);
}

// round 9
// speedup vs baseline: 1.6669x; 1.6669x over previous
#include <cuda_runtime.h>
#include <cuda_bf16.h>
#include <math.h>

#define B_  2
#define S_  2048
#define E_  512
#define NH_ 4
#define DH_ 128
#define R_  (B_*S_)

// ------------------------- device scratch -------------------------
__device__ float g_xm  [R_*E_];
__device__ float g_zsil[R_*E_];
__device__ float g_xc  [R_*E_];
__device__ float g_q   [R_*E_];
__device__ float g_k   [R_*E_];
__device__ float g_v   [R_*E_];
__device__ float g_h   [R_*E_];
__device__ float g_hs  [R_*E_];
__device__ float g_Wt  [E_*4*E_];          // [o][tap*512+i]
__device__ float g_ig  [B_*NH_*S_];
__device__ float g_fg  [B_*NH_*S_];
__device__ float g_dkey[B_*NH_*S_];
__device__ float g_mrow[B_*NH_*S_];
__device__ float g_mexp[B_*NH_*S_];

// ------------------------- helpers -------------------------
__device__ __forceinline__ float tf32r(float x){
  unsigned u; asm("cvt.rna.tf32.f32 %0, %1;" : "=r"(u) : "f"(x));
  return __uint_as_float(u);
}
__device__ __forceinline__ void mma8(float c[4], const unsigned a[4], const unsigned b[2]){
  asm volatile("mma.sync.aligned.m16n8k8.row.col.f32.tf32.tf32.f32 "
    "{%0,%1,%2,%3}, {%4,%5,%6,%7}, {%8,%9}, {%0,%1,%2,%3};"
    : "+f"(c[0]),"+f"(c[1]),"+f"(c[2]),"+f"(c[3])
    : "r"(a[0]),"r"(a[1]),"r"(a[2]),"r"(a[3]), "r"(b[0]),"r"(b[1]));
}
__device__ __forceinline__ float silu(float x){ return x/(1.f+__expf(-x)); }
// split float4 into tf32 hi + tf32 lo, write both
__device__ __forceinline__ void sp4(float* hi, float* lo, float4 v){
  float h0=tf32r(v.x), h1=tf32r(v.y), h2=tf32r(v.z), h3=tf32r(v.w);
  *(float4*)hi = make_float4(h0,h1,h2,h3);
  *(float4*)lo = make_float4(tf32r(v.x-h0),tf32r(v.y-h1),tf32r(v.z-h2),tf32r(v.w-h3));
}

// ---------------- conv weight repack: Wt[o][tap*512+i] ----------------
__global__ void k_wt(const float* __restrict__ conv_w){
  int o = blockIdx.x; int i = threadIdx.x;
  #pragma unroll
  for (int tap=0;tap<4;tap++)
    g_Wt[(size_t)o*2048 + tap*512 + i] = conv_w[((size_t)o*512+i)*4 + tap];
}

// ---------------- shared 3xTF32 mma GEMM core ----------------
// C[128,128]: A[128,K] row-major, W[128 N-rows, K] row-major.
// 256 thr, 8 warps 4x2, warp tile 32x64.
#define PADK 20
__device__ __forceinline__ void mm_core3(
    const float* __restrict__ A, int lda,
    const float* __restrict__ W, int ldw, int K,
    float (*Ah)[PADK], float (*Al)[PADK], float (*Bh)[PADK], float (*Bl)[PADK],
    float acc[2][8][4])
{
  const int tid=threadIdx.x, warp=tid>>5, lane=tid&31, gid=lane>>2, tig=lane&3;
  const int wm=(warp>>1)*32, wn=(warp&1)*64;
  const int m0=tid>>2, m1=m0+64, c0=(tid&3)*4;
  for (int k0=0;k0<K;k0+=16){
    sp4(&Ah[m0][c0], &Al[m0][c0], *(const float4*)&A[(size_t)m0*lda+k0+c0]);
    sp4(&Ah[m1][c0], &Al[m1][c0], *(const float4*)&A[(size_t)m1*lda+k0+c0]);
    sp4(&Bh[m0][c0], &Bl[m0][c0], *(const float4*)&W[(size_t)m0*ldw+k0+c0]);
    sp4(&Bh[m1][c0], &Bl[m1][c0], *(const float4*)&W[(size_t)m1*ldw+k0+c0]);
    __syncthreads();
    #pragma unroll
    for (int kk=0;kk<16;kk+=8){
      unsigned ah[2][4], al[2][4];
      #pragma unroll
      for (int mt=0;mt<2;mt++){
        int r = wm+mt*16+gid;
        ah[mt][0]=__float_as_uint(Ah[r  ][kk+tig  ]);
        ah[mt][1]=__float_as_uint(Ah[r+8][kk+tig  ]);
        ah[mt][2]=__float_as_uint(Ah[r  ][kk+tig+4]);
        ah[mt][3]=__float_as_uint(Ah[r+8][kk+tig+4]);
        al[mt][0]=__float_as_uint(Al[r  ][kk+tig  ]);
        al[mt][1]=__float_as_uint(Al[r+8][kk+tig  ]);
        al[mt][2]=__float_as_uint(Al[r  ][kk+tig+4]);
        al[mt][3]=__float_as_uint(Al[r+8][kk+tig+4]);
      }
      #pragma unroll
      for (int nt=0;nt<8;nt++){
        int cc = wn+nt*8+gid;
        unsigned bh2[2], bl2[2];
        bh2[0]=__float_as_uint(Bh[cc][kk+tig  ]);
        bh2[1]=__float_as_uint(Bh[cc][kk+tig+4]);
        bl2[0]=__float_as_uint(Bl[cc][kk+tig  ]);
        bl2[1]=__float_as_uint(Bl[cc][kk+tig+4]);
        #pragma unroll
        for (int mt=0;mt<2;mt++){
          mma8(acc[mt][nt], al[mt], bh2);
          mma8(acc[mt][nt], ah[mt], bl2);
          mma8(acc[mt][nt], ah[mt], bh2);
        }
      }
    }
    __syncthreads();
  }
}

#define EPI_COORDS \
  const int tid=threadIdx.x, warp=tid>>5, lane=tid&31, gid=lane>>2, tig=lane&3; \
  const int wm=(warp>>1)*32, wn=(warp&1)*64; (void)wm; (void)tid;

// ---------------- up projection ----------------
__global__ __launch_bounds__(256) void k_up(const float* __restrict__ X,
                                            const float* __restrict__ Wup){
  __shared__ float Ah[128][PADK], Al[128][PADK], Bh[128][PADK], Bl[128][PADK];
  int bm = blockIdx.y*128, bn = blockIdx.x*128;
  float acc[2][8][4];
  #pragma unroll
  for(int i=0;i<2;i++)for(int j=0;j<8;j++)for(int e=0;e<4;e++)acc[i][j][e]=0;
  mm_core3(X+(size_t)bm*512, 512, Wup+(size_t)bn*512, 512, 512, Ah,Al,Bh,Bl, acc);
  EPI_COORDS;
  bool is_z = (bn >= 512);
  #pragma unroll
  for (int mt=0;mt<2;mt++){
    #pragma unroll
    for (int nt=0;nt<8;nt++){
      int row = bm+wm+mt*16+gid;
      int col = bn+wn+nt*8+tig*2;
      float* c = acc[mt][nt];
      if (!is_z){
        *(float2*)&g_xm[(size_t)row*512+col]     = make_float2(c[0],c[1]);
        *(float2*)&g_xm[(size_t)(row+8)*512+col] = make_float2(c[2],c[3]);
      } else {
        int cz = col-512;
        *(float2*)&g_zsil[(size_t)row*512+cz]     = make_float2(silu(c[0]),silu(c[1]));
        *(float2*)&g_zsil[(size_t)(row+8)*512+cz] = make_float2(silu(c[2]),silu(c[3]));
      }
    }
  }
}

// ---------------- causal conv1d as shifted GEMM + silu ----------------
__global__ __launch_bounds__(256) void k_conv(const float* __restrict__ convb){
  __shared__ float Ah[128][PADK], Al[128][PADK], Bh[128][PADK], Bl[128][PADK];
  int bm = blockIdx.y*128, bn = blockIdx.x*128;
  const int tid=threadIdx.x, warp=tid>>5, lane=tid&31, gid=lane>>2, tig=lane&3;
  const int wm=(warp>>1)*32, wn=(warp&1)*64;
  const int m0=tid>>2, m1=m0+64, c0=(tid&3)*4;
  const int s0 = (bm+m0)&(S_-1), s1 = (bm+m1)&(S_-1);
  float acc[2][8][4];
  #pragma unroll
  for(int i=0;i<2;i++)for(int j=0;j<8;j++)for(int e=0;e<4;e++)acc[i][j][e]=0;
  const float* W = g_Wt + (size_t)bn*2048;
  for (int k0=0;k0<2048;k0+=16){
    int tap = k0>>9, i0 = k0&511;
    float4 a0 = (s0+tap-3>=0) ? *(const float4*)&g_xm[(size_t)(bm+m0+tap-3)*512 + i0 + c0]
                              : make_float4(0,0,0,0);
    float4 a1 = (s1+tap-3>=0) ? *(const float4*)&g_xm[(size_t)(bm+m1+tap-3)*512 + i0 + c0]
                              : make_float4(0,0,0,0);
    sp4(&Ah[m0][c0], &Al[m0][c0], a0);
    sp4(&Ah[m1][c0], &Al[m1][c0], a1);
    sp4(&Bh[m0][c0], &Bl[m0][c0], *(const float4*)&W[(size_t)m0*2048 + k0 + c0]);
    sp4(&Bh[m1][c0], &Bl[m1][c0], *(const float4*)&W[(size_t)m1*2048 + k0 + c0]);
    __syncthreads();
    #pragma unroll
    for (int kk=0;kk<16;kk+=8){
      unsigned ah[2][4], al[2][4];
      #pragma unroll
      for (int mt=0;mt<2;mt++){
        int r = wm+mt*16+gid;
        ah[mt][0]=__float_as_uint(Ah[r  ][kk+tig  ]);
        ah[mt][1]=__float_as_uint(Ah[r+8][kk+tig  ]);
        ah[mt][2]=__float_as_uint(Ah[r  ][kk+tig+4]);
        ah[mt][3]=__float_as_uint(Ah[r+8][kk+tig+4]);
        al[mt][0]=__float_as_uint(Al[r  ][kk+tig  ]);
        al[mt][1]=__float_as_uint(Al[r+8][kk+tig  ]);
        al[mt][2]=__float_as_uint(Al[r  ][kk+tig+4]);
        al[mt][3]=__float_as_uint(Al[r+8][kk+tig+4]);
      }
      #pragma unroll
      for (int nt=0;nt<8;nt++){
        int cc = wn+nt*8+gid;
        unsigned bh2[2], bl2[2];
        bh2[0]=__float_as_uint(Bh[cc][kk+tig  ]);
        bh2[1]=__float_as_uint(Bh[cc][kk+tig+4]);
        bl2[0]=__float_as_uint(Bl[cc][kk+tig  ]);
        bl2[1]=__float_as_uint(Bl[cc][kk+tig+4]);
        #pragma unroll
        for (int mt=0;mt<2;mt++){
          mma8(acc[mt][nt], al[mt], bh2);
          mma8(acc[mt][nt], ah[mt], bl2);
          mma8(acc[mt][nt], ah[mt], bh2);
        }
      }
    }
    __syncthreads();
  }
  #pragma unroll
  for (int mt=0;mt<2;mt++){
    #pragma unroll
    for (int nt=0;nt<8;nt++){
      int row = bm+wm+mt*16+gid;
      int col = bn+wn+nt*8+tig*2;
      float b0 = convb[col], b1 = convb[col+1];
      float* c = acc[mt][nt];
      *(float2*)&g_xc[(size_t)row*512+col]     = make_float2(silu(c[0]+b0),silu(c[1]+b1));
      *(float2*)&g_xc[(size_t)(row+8)*512+col] = make_float2(silu(c[2]+b0),silu(c[3]+b1));
    }
  }
}

// ---------------- headwise q/k/v ----------------
__global__ __launch_bounds__(256) void k_qkv(const float* __restrict__ Wq,
                                             const float* __restrict__ Wk,
                                             const float* __restrict__ Wv){
  __shared__ float Ah[128][PADK], Al[128][PADK], Bh[128][PADK], Bl[128][PADK];
  int zz = blockIdx.z; int op = zz>>2; int h = zz&3;
  const float* A  = (op==2 ? g_xm : g_xc) + h*128;
  const float* Wp = (op==0 ? Wq : (op==1 ? Wk : Wv)) + (size_t)h*128*128;
  float* Cp = (op==0 ? g_q : (op==1 ? g_k : g_v)) + h*128;
  int bm = blockIdx.y*128;
  float acc[2][8][4];
  #pragma unroll
  for(int i=0;i<2;i++)for(int j=0;j<8;j++)for(int e=0;e<4;e++)acc[i][j][e]=0;
  mm_core3(A+(size_t)bm*512, 512, Wp, 128, 128, Ah,Al,Bh,Bl, acc);
  EPI_COORDS;
  #pragma unroll
  for (int mt=0;mt<2;mt++){
    #pragma unroll
    for (int nt=0;nt<8;nt++){
      int row = bm+wm+mt*16+gid;
      int col = wn+nt*8+tig*2;
      float* c = acc[mt][nt];
      *(float2*)&Cp[(size_t)row*512+col]     = make_float2(c[0],c[1]);
      *(float2*)&Cp[(size_t)(row+8)*512+col] = make_float2(c[2],c[3]);
    }
  }
}

// ---------------- down projection + bias ----------------
__global__ __launch_bounds__(256) void k_down(const float* __restrict__ Wd,
                                              const float* __restrict__ bd,
                                              float* __restrict__ out){
  __shared__ float Ah[128][PADK], Al[128][PADK], Bh[128][PADK], Bl[128][PADK];
  int bm = blockIdx.y*128, bn = blockIdx.x*128;
  float acc[2][8][4];
  #pragma unroll
  for(int i=0;i<2;i++)for(int j=0;j<8;j++)for(int e=0;e<4;e++)acc[i][j][e]=0;
  mm_core3(g_hs+(size_t)bm*512, 512, Wd+(size_t)bn*512, 512, 512, Ah,Al,Bh,Bl, acc);
  EPI_COORDS;
  #pragma unroll
  for (int mt=0;mt<2;mt++){
    #pragma unroll
    for (int nt=0;nt<8;nt++){
      int row = bm+wm+mt*16+gid;
      int col = bn+wn+nt*8+tig*2;
      float b0 = bd[col], b1 = bd[col+1];
      float* c = acc[mt][nt];
      *(float2*)&out[(size_t)row*512+col]     = make_float2(c[0]+b0,c[1]+b1);
      *(float2*)&out[(size_t)(row+8)*512+col] = make_float2(c[2]+b0,c[3]+b1);
    }
  }
}

// ---------------- gate projections ----------------
__global__ void k_gates(const float* __restrict__ Wi, const float* __restrict__ bi,
                        const float* __restrict__ Wf, const float* __restrict__ bf){
  int r = blockIdx.x; int tid = threadIdx.x;
  float pi[4]={0,0,0,0}, pf[4]={0,0,0,0};
  const float* qr = g_q + (size_t)r*512;
  const float* kr = g_k + (size_t)r*512;
  const float* vr = g_v + (size_t)r*512;
  for (int e=tid; e<512; e+=128){
    float a=qr[e], c=kr[e], d=vr[e];
    #pragma unroll
    for (int h=0;h<4;h++){
      const float* wih = Wi + h*1536; const float* wfh = Wf + h*1536;
      pi[h] += a*wih[e] + c*wih[512+e] + d*wih[1024+e];
      pf[h] += a*wfh[e] + c*wfh[512+e] + d*wfh[1024+e];
    }
  }
  __shared__ float red[8][128];
  #pragma unroll
  for (int h=0;h<4;h++){ red[h][tid]=pi[h]; red[4+h][tid]=pf[h]; }
  __syncthreads();
  for (int sft=64; sft>=1; sft>>=1){
    if (tid < sft){
      #pragma unroll
      for (int a=0;a<8;a++) red[a][tid]+=red[a][tid+sft];
    }
    __syncthreads();
  }
  if (tid < 4){
    int b = r>>11, s = r&2047;
    g_ig[((size_t)b*4+tid)*2048 + s] = red[tid][0]   + bi[tid];
    g_fg[((size_t)b*4+tid)*2048 + s] = red[4+tid][0] + bf[tid];
  }
}

// ---------------- per-(b,h) scan ----------------
__global__ void k_scan(){
  int bh = blockIdx.x; int t = threadIdx.x;
  const float* fg = g_fg + (size_t)bh*2048;
  const float* ig = g_ig + (size_t)bh*2048;
  double lcum[8]; double run = 0.0;
  #pragma unroll
  for (int u=0;u<8;u++){
    double x = (double)fg[t*8+u];
    double ls = (x < 0.0) ? (x - log1p(exp(x))) : (-log1p(exp(-x)));
    run += ls; lcum[u] = run;
  }
  __shared__ double sh[256];
  sh[t] = run; __syncthreads();
  for (int off=1; off<256; off<<=1){
    double cur = sh[t]; double oth = (t>=off)? sh[t-off] : 0.0;
    __syncthreads(); sh[t] = cur + oth; __syncthreads();
  }
  double base = (t>0)? sh[t-1] : 0.0;
  double dv[8], lf[8]; double runm = -1e300;
  #pragma unroll
  for (int u=0;u<8;u++){
    double lfc = base + lcum[u];
    lf[u] = lfc; dv[u] = (double)ig[t*8+u] - lfc;
    if (dv[u] > runm) runm = dv[u];
  }
  __syncthreads();
  sh[t] = runm; __syncthreads();
  for (int off=1; off<256; off<<=1){
    double cur = sh[t]; double oth = (t>=off)? sh[t-off] : -1e300;
    __syncthreads(); sh[t] = (cur>oth)?cur:oth; __syncthreads();
  }
  double basem = (t>0)? sh[t-1] : -1e300;
  double rm = basem;
  #pragma unroll
  for (int u=0;u<8;u++){
    if (dv[u] > rm) rm = dv[u];
    int j = bh*2048 + t*8 + u;
    g_dkey[j] = (float)dv[u];
    g_mrow[j] = (float)rm;
    g_mexp[j] = (float)exp(-(lf[u] + rm));
  }
}

// ---------------- 3xTF32 flash causal mLSTM attention ----------------
// floats: QH[64*132] QL[64*132] | buf (K hi/lo 2*64*132, reused V hi/lo 2*64*136)
//         | SSH[64*68] SSL[64*68] | dk[64] red[128] sinv[64]
#define OFF_QH   0
#define OFF_QL   (64*132)
#define OFF_BUF  (2*64*132)
#define BUF_SZ   (2*64*136)
#define OFF_SSH  (OFF_BUF + BUF_SZ)
#define OFF_SSL  (OFF_SSH + 64*68)
#define OFF_DK   (OFF_SSL + 64*68)
#define OFF_RED  (OFF_DK + 64)
#define OFF_SINV (OFF_RED + 128)
#define ATT_FLOATS (OFF_SINV + 64)
#define ATT_SMEM (ATT_FLOATS*4)

__global__ __launch_bounds__(256) void k_attn(){
  extern __shared__ float sm[];
  float* QH = sm + OFF_QH;
  float* QL = sm + OFF_QL;
  float* KH = sm + OFF_BUF;            // stride 132
  float* KL = KH + 64*132;
  float* VH = sm + OFF_BUF;            // stride 136 (aliases K region)
  float* VL = VH + 64*136;
  float* SSH = sm + OFF_SSH;
  float* SSL = sm + OFF_SSL;
  float* dks = sm + OFF_DK;
  float* red = sm + OFF_RED;
  float* sinv= sm + OFF_SINV;

  int bh = blockIdx.y; int b = bh>>2, h = bh&3;
  int it = (int)gridDim.x - 1 - (int)blockIdx.x;
  int i0 = it*64;
  const int tid=threadIdx.x, warp=tid>>5, lane=tid&31, gid=lane>>2, tig=lane&3;
  const int wr=warp>>1, wc=warp&1;
  const int qm = wr*16;
  const float scale = 0.08838834764831845f;

  const float* qbase = g_q + ((size_t)(b*2048 + i0))*512 + h*128;
  #pragma unroll
  for (int u=0;u<8;u++){
    int idx = tid + u*256;
    int row = idx>>5, c4 = (idx&31)*4;
    sp4(&QH[row*132+c4], &QL[row*132+c4], *(const float4*)&qbase[(size_t)row*512 + c4]);
  }
  float mr0 = g_mrow[bh*2048 + i0 + qm + gid];
  float mr1 = g_mrow[bh*2048 + i0 + qm + gid + 8];

  float oacc[8][4];
  #pragma unroll
  for (int nt=0;nt<8;nt++){oacc[nt][0]=0;oacc[nt][1]=0;oacc[nt][2]=0;oacc[nt][3]=0;}
  float psum0 = 0.f, psum1 = 0.f;

  for (int j0 = 0; j0 <= i0; j0 += 64){
    __syncthreads();
    const float* kbase = g_k + ((size_t)(b*2048 + j0))*512 + h*128;
    #pragma unroll
    for (int u=0;u<8;u++){
      int idx = tid + u*256;
      int row = idx>>5, c4 = (idx&31)*4;
      sp4(&KH[row*132+c4], &KL[row*132+c4], *(const float4*)&kbase[(size_t)row*512 + c4]);
    }
    if (tid < 64) dks[tid] = g_dkey[bh*2048 + j0 + tid];
    __syncthreads();

    // QK^T 3x: warp rows qm..qm+15, key cols wc*32..+31
    float sacc[4][4];
    #pragma unroll
    for (int nt=0;nt<4;nt++){sacc[nt][0]=0;sacc[nt][1]=0;sacc[nt][2]=0;sacc[nt][3]=0;}
    #pragma unroll
    for (int kk=0;kk<128;kk+=8){
      unsigned ah[4], al[4];
      ah[0]=__float_as_uint(QH[(qm+gid  )*132 + kk+tig  ]);
      ah[1]=__float_as_uint(QH[(qm+gid+8)*132 + kk+tig  ]);
      ah[2]=__float_as_uint(QH[(qm+gid  )*132 + kk+tig+4]);
      ah[3]=__float_as_uint(QH[(qm+gid+8)*132 + kk+tig+4]);
      al[0]=__float_as_uint(QL[(qm+gid  )*132 + kk+tig  ]);
      al[1]=__float_as_uint(QL[(qm+gid+8)*132 + kk+tig  ]);
      al[2]=__float_as_uint(QL[(qm+gid  )*132 + kk+tig+4]);
      al[3]=__float_as_uint(QL[(qm+gid+8)*132 + kk+tig+4]);
      #pragma unroll
      for (int nt=0;nt<4;nt++){
        int jr = wc*32+nt*8+gid;
        unsigned bh2[2], bl2[2];
        bh2[0]=__float_as_uint(KH[jr*132 + kk+tig  ]);
        bh2[1]=__float_as_uint(KH[jr*132 + kk+tig+4]);
        bl2[0]=__float_as_uint(KL[jr*132 + kk+tig  ]);
        bl2[1]=__float_as_uint(KL[jr*132 + kk+tig+4]);
        mma8(sacc[nt], al, bh2);
        mma8(sacc[nt], ah, bl2);
        mma8(sacc[nt], ah, bh2);
      }
    }
    bool diag = (j0 == i0);
    #pragma unroll
    for (int nt=0;nt<4;nt++){
      int jl = wc*32+nt*8+tig*2;
      float d0 = dks[jl], d1 = dks[jl+1];
      int il0 = qm+gid, il1 = il0+8;
      float s00 = sacc[nt][0]*scale*__expf(d0 - mr0);
      float s01 = sacc[nt][1]*scale*__expf(d1 - mr0);
      float s10 = sacc[nt][2]*scale*__expf(d0 - mr1);
      float s11 = sacc[nt][3]*scale*__expf(d1 - mr1);
      if (diag){
        if (jl   > il0) s00 = 0.f;
        if (jl+1 > il0) s01 = 0.f;
        if (jl   > il1) s10 = 0.f;
        if (jl+1 > il1) s11 = 0.f;
      }
      psum0 += s00 + s01;
      psum1 += s10 + s11;
      float h00=tf32r(s00), h01=tf32r(s01), h10=tf32r(s10), h11=tf32r(s11);
      *(float2*)&SSH[il0*68 + jl] = make_float2(h00, h01);
      *(float2*)&SSH[il1*68 + jl] = make_float2(h10, h11);
      *(float2*)&SSL[il0*68 + jl] = make_float2(tf32r(s00-h00), tf32r(s01-h01));
      *(float2*)&SSL[il1*68 + jl] = make_float2(tf32r(s10-h10), tf32r(s11-h11));
    }
    __syncthreads();                       // K consumed, S ready

    // V tiles, row-major stride 136 (hi/lo), aliasing K region
    const float* vbase = g_v + ((size_t)(b*2048 + j0))*512 + h*128;
    #pragma unroll
    for (int u=0;u<8;u++){
      int idx = tid + u*256;
      int j = idx>>5, d0 = (idx&31)*4;
      sp4(&VH[j*136+d0], &VL[j*136+d0], *(const float4*)&vbase[(size_t)j*512 + d0]);
    }
    __syncthreads();

    // S @ V 3x: rows qm..qm+15, d cols wc*64..+63
    #pragma unroll
    for (int kk=0;kk<64;kk+=8){
      unsigned ah[4], al[4];
      ah[0]=__float_as_uint(SSH[(qm+gid  )*68 + kk+tig  ]);
      ah[1]=__float_as_uint(SSH[(qm+gid+8)*68 + kk+tig  ]);
      ah[2]=__float_as_uint(SSH[(qm+gid  )*68 + kk+tig+4]);
      ah[3]=__float_as_uint(SSH[(qm+gid+8)*68 + kk+tig+4]);
      al[0]=__float_as_uint(SSL[(qm+gid  )*68 + kk+tig  ]);
      al[1]=__float_as_uint(SSL[(qm+gid+8)*68 + kk+tig  ]);
      al[2]=__float_as_uint(SSL[(qm+gid  )*68 + kk+tig+4]);
      al[3]=__float_as_uint(SSL[(qm+gid+8)*68 + kk+tig+4]);
      #pragma unroll
      for (int nt=0;nt<8;nt++){
        int dc = wc*64+nt*8+gid;
        unsigned bh2[2], bl2[2];
        bh2[0]=__float_as_uint(VH[(kk+tig  )*136 + dc]);
        bh2[1]=__float_as_uint(VH[(kk+tig+4)*136 + dc]);
        bl2[0]=__float_as_uint(VL[(kk+tig  )*136 + dc]);
        bl2[1]=__float_as_uint(VL[(kk+tig+4)*136 + dc]);
        mma8(oacc[nt], al, bh2);
        mma8(oacc[nt], ah, bl2);
        mma8(oacc[nt], ah, bh2);
      }
    }
  }

  // normalizer
  psum0 += __shfl_xor_sync(0xffffffffu, psum0, 1);
  psum0 += __shfl_xor_sync(0xffffffffu, psum0, 2);
  psum1 += __shfl_xor_sync(0xffffffffu, psum1, 1);
  psum1 += __shfl_xor_sync(0xffffffffu, psum1, 2);
  if (tig == 0){
    red[(qm+gid)*2   + wc] = psum0;
    red[(qm+gid+8)*2 + wc] = psum1;
  }
  __syncthreads();
  if (tid < 64){
    float s2 = red[tid*2] + red[tid*2+1];
    float nrm = fmaxf(fabsf(s2), g_mexp[bh*2048 + i0 + tid]);
    sinv[tid] = 1.f/(nrm + 1e-6f);
  }
  __syncthreads();

  float iv0 = sinv[qm+gid], iv1 = sinv[qm+gid+8];
  float* obase = g_h + ((size_t)(b*2048 + i0))*512 + h*128;
  #pragma unroll
  for (int nt=0;nt<8;nt++){
    int col = wc*64+nt*8+tig*2;
    *(float2*)&obase[(size_t)(qm+gid)*512 + col] =
      make_float2(oacc[nt][0]*iv0, oacc[nt][1]*iv0);
    *(float2*)&obase[(size_t)(qm+gid+8)*512 + col] =
      make_float2(oacc[nt][2]*iv1, oacc[nt][3]*iv1);
  }
}

// ---------------- groupnorm + skip + z-gate ----------------
__global__ void k_norm(const float* __restrict__ skip){
  int r = blockIdx.x; int t = threadIdx.x;
  float v[4];
  #pragma unroll
  for (int h=0;h<4;h++) v[h] = g_h[(size_t)r*512 + h*128 + t];
  __shared__ float rs[4][128], rq[4][128];
  #pragma unroll
  for (int h=0;h<4;h++){ rs[h][t]=v[h]; rq[h][t]=v[h]*v[h]; }
  __syncthreads();
  for (int sft=64; sft>=1; sft>>=1){
    if (t < sft){
      #pragma unroll
      for (int h=0;h<4;h++){ rs[h][t]+=rs[h][t+sft]; rq[h][t]+=rq[h][t+sft]; }
    }
    __syncthreads();
  }
  #pragma unroll
  for (int h=0;h<4;h++){
    float mean = rs[h][0]*(1.f/128.f);
    float var  = rq[h][0]*(1.f/128.f) - mean*mean;
    float hn = (v[h]-mean)*rsqrtf(var + 1e-5f);
    int e = h*128 + t;
    float hskip = hn + skip[e]*g_xc[(size_t)r*512 + e];
    g_hs[(size_t)r*512 + e] = hskip * g_zsil[(size_t)r*512 + e];
  }
}

// ---------------- launch ----------------
extern "C" void kernel_launch(void* const* d_in, const int* in_sizes, int n_in,
                              void* d_out, int out_size){
  const float* x      = (const float*)d_in[0];
  const float* W_up   = (const float*)d_in[1];
  const float* Wq     = (const float*)d_in[2];
  const float* Wk     = (const float*)d_in[3];
  const float* Wv     = (const float*)d_in[4];
  const float* conv_w = (const float*)d_in[5];
  const float* conv_b = (const float*)d_in[6];
  const float* Wi     = (const float*)d_in[7];
  const float* bi     = (const float*)d_in[8];
  const float* Wf     = (const float*)d_in[9];
  const float* bf     = (const float*)d_in[10];
  const float* skip   = (const float*)d_in[11];
  const float* W_down = (const float*)d_in[12];
  const float* b_down = (const float*)d_in[13];
  float* out = (float*)d_out;

  static bool attr_set = false;
  if (!attr_set){
    cudaFuncSetAttribute(k_attn, cudaFuncAttributeMaxDynamicSharedMemorySize, ATT_SMEM);
    attr_set = true;
  }

  k_wt  <<<512, 512>>>(conv_w);
  k_up  <<<dim3(8,32), 256>>>(x, W_up);
  k_conv<<<dim3(4,32), 256>>>(conv_b);
  k_qkv <<<dim3(1,32,12), 256>>>(Wq, Wk, Wv);
  k_gates<<<4096,128>>>(Wi, bi, Wf, bf);
  k_scan<<<8,256>>>();
  k_attn<<<dim3(32,8),256, ATT_SMEM>>>();
  k_norm<<<4096,128>>>(skip);
  k_down<<<dim3(4,32),256>>>(W_down, b_down, out);
}

// round 13
// speedup vs baseline: 1.8860x; 1.1314x over previous
#include <cuda_runtime.h>
#include <cuda_bf16.h>
#include <math.h>

#define B_  2
#define S_  2048
#define E_  512
#define NH_ 4
#define DH_ 128
#define R_  (B_*S_)

// ------------------------- device scratch -------------------------
__device__ float g_xm  [R_*E_];
__device__ float g_zsil[R_*E_];
__device__ float g_xc  [R_*E_];
__device__ float g_q   [R_*E_];
__device__ float g_k   [R_*E_];
__device__ float g_v   [R_*E_];
__device__ float g_h   [R_*E_];
__device__ float g_hs  [R_*E_];
__device__ float g_Wt  [E_*4*E_];          // [o][tap*512+i]
__device__ float g_ig  [B_*NH_*S_];
__device__ float g_fg  [B_*NH_*S_];
__device__ float g_dkey[B_*NH_*S_];
__device__ float g_mrow[B_*NH_*S_];
__device__ float g_mexp[B_*NH_*S_];

// ------------------------- helpers -------------------------
__device__ __forceinline__ float tf32r(float x){
  unsigned u; asm("cvt.rna.tf32.f32 %0, %1;" : "=r"(u) : "f"(x));
  return __uint_as_float(u);
}
__device__ __forceinline__ void mma8(float c[4], const unsigned a[4], const unsigned b[2]){
  asm volatile("mma.sync.aligned.m16n8k8.row.col.f32.tf32.tf32.f32 "
    "{%0,%1,%2,%3}, {%4,%5,%6,%7}, {%8,%9}, {%0,%1,%2,%3};"
    : "+f"(c[0]),"+f"(c[1]),"+f"(c[2]),"+f"(c[3])
    : "r"(a[0]),"r"(a[1]),"r"(a[2]),"r"(a[3]), "r"(b[0]),"r"(b[1]));
}
__device__ __forceinline__ float silu(float x){ return x/(1.f+__expf(-x)); }
__device__ __forceinline__ void sp4(float* hi, float* lo, float4 v){
  float h0=tf32r(v.x), h1=tf32r(v.y), h2=tf32r(v.z), h3=tf32r(v.w);
  *(float4*)hi = make_float4(h0,h1,h2,h3);
  *(float4*)lo = make_float4(tf32r(v.x-h0),tf32r(v.y-h1),tf32r(v.z-h2),tf32r(v.w-h3));
}

// ---------------- conv weight repack: Wt[o][tap*512+i] ----------------
__global__ void k_wt(const float* __restrict__ conv_w){
  int o = blockIdx.x; int i = threadIdx.x;
  #pragma unroll
  for (int tap=0;tap<4;tap++)
    g_Wt[(size_t)o*2048 + tap*512 + i] = conv_w[((size_t)o*512+i)*4 + tap];
}

// ---------------- pipelined 3xTF32 mma GEMM core ----------------
// C[128,128]: A[128,K] row-major, W[128 N-rows, K] row-major.
// 256 thr, 8 warps 4x2, warp tile 32x64; 2-stage smem double buffer.
#define PADK   20
#define TILEF  (128*PADK)       // 2560 floats
#define GSTAGE (4*TILEF)        // Ah,Al,Bh,Bl per stage
#define GEMM_SMEM (2*GSTAGE*4)  // 81920 bytes

// compute one 16-k slice from stage base
__device__ __forceinline__ void mm_slice(
    const float* Ah, const float* Al, const float* Bh, const float* Bl,
    int wm, int wn, int gid, int tig, float acc[2][8][4])
{
  #pragma unroll
  for (int kk=0;kk<16;kk+=8){
    unsigned ah[2][4], al[2][4];
    #pragma unroll
    for (int mt=0;mt<2;mt++){
      int r = wm+mt*16+gid;
      ah[mt][0]=__float_as_uint(Ah[(r  )*PADK + kk+tig  ]);
      ah[mt][1]=__float_as_uint(Ah[(r+8)*PADK + kk+tig  ]);
      ah[mt][2]=__float_as_uint(Ah[(r  )*PADK + kk+tig+4]);
      ah[mt][3]=__float_as_uint(Ah[(r+8)*PADK + kk+tig+4]);
      al[mt][0]=__float_as_uint(Al[(r  )*PADK + kk+tig  ]);
      al[mt][1]=__float_as_uint(Al[(r+8)*PADK + kk+tig  ]);
      al[mt][2]=__float_as_uint(Al[(r  )*PADK + kk+tig+4]);
      al[mt][3]=__float_as_uint(Al[(r+8)*PADK + kk+tig+4]);
    }
    #pragma unroll
    for (int nt=0;nt<8;nt++){
      int cc = wn+nt*8+gid;
      unsigned bh2[2], bl2[2];
      bh2[0]=__float_as_uint(Bh[cc*PADK + kk+tig  ]);
      bh2[1]=__float_as_uint(Bh[cc*PADK + kk+tig+4]);
      bl2[0]=__float_as_uint(Bl[cc*PADK + kk+tig  ]);
      bl2[1]=__float_as_uint(Bl[cc*PADK + kk+tig+4]);
      #pragma unroll
      for (int mt=0;mt<2;mt++){
        mma8(acc[mt][nt], al[mt], bh2);
        mma8(acc[mt][nt], ah[mt], bl2);
        mma8(acc[mt][nt], ah[mt], bh2);
      }
    }
  }
}

__device__ __forceinline__ void mm_core3p(
    const float* __restrict__ A, int lda,
    const float* __restrict__ W, int ldw, int K,
    float* __restrict__ sm, float acc[2][8][4])
{
  const int tid=threadIdx.x, warp=tid>>5, lane=tid&31, gid=lane>>2, tig=lane&3;
  const int wm=(warp>>1)*32, wn=(warp&1)*64;
  const int m0=tid>>2, m1=m0+64, c0=(tid&3)*4;
  float4 ra0 = *(const float4*)&A[(size_t)m0*lda + c0];
  float4 ra1 = *(const float4*)&A[(size_t)m1*lda + c0];
  float4 rb0 = *(const float4*)&W[(size_t)m0*ldw + c0];
  float4 rb1 = *(const float4*)&W[(size_t)m1*ldw + c0];
  int buf = 0;
  for (int k0=0;k0<K;k0+=16){
    float* Ah = sm + buf*GSTAGE;
    float* Al = Ah + TILEF;
    float* Bh = Al + TILEF;
    float* Bl = Bh + TILEF;
    sp4(&Ah[m0*PADK+c0], &Al[m0*PADK+c0], ra0);
    sp4(&Ah[m1*PADK+c0], &Al[m1*PADK+c0], ra1);
    sp4(&Bh[m0*PADK+c0], &Bl[m0*PADK+c0], rb0);
    sp4(&Bh[m1*PADK+c0], &Bl[m1*PADK+c0], rb1);
    __syncthreads();
    if (k0+16 < K){
      ra0 = *(const float4*)&A[(size_t)m0*lda + k0+16 + c0];
      ra1 = *(const float4*)&A[(size_t)m1*lda + k0+16 + c0];
      rb0 = *(const float4*)&W[(size_t)m0*ldw + k0+16 + c0];
      rb1 = *(const float4*)&W[(size_t)m1*ldw + k0+16 + c0];
    }
    mm_slice(Ah,Al,Bh,Bl, wm,wn,gid,tig, acc);
    buf ^= 1;
  }
}

#define EPI_COORDS \
  const int tid=threadIdx.x, warp=tid>>5, lane=tid&31, gid=lane>>2, tig=lane&3; \
  const int wm=(warp>>1)*32, wn=(warp&1)*64; (void)wm; (void)tid;

// ---------------- up projection ----------------
__global__ __launch_bounds__(256) void k_up(const float* __restrict__ X,
                                            const float* __restrict__ Wup){
  extern __shared__ float smdyn[];
  int bm = blockIdx.y*128, bn = blockIdx.x*128;
  float acc[2][8][4];
  #pragma unroll
  for(int i=0;i<2;i++)for(int j=0;j<8;j++)for(int e=0;e<4;e++)acc[i][j][e]=0;
  mm_core3p(X+(size_t)bm*512, 512, Wup+(size_t)bn*512, 512, 512, smdyn, acc);
  EPI_COORDS;
  bool is_z = (bn >= 512);
  #pragma unroll
  for (int mt=0;mt<2;mt++){
    #pragma unroll
    for (int nt=0;nt<8;nt++){
      int row = bm+wm+mt*16+gid;
      int col = bn+wn+nt*8+tig*2;
      float* c = acc[mt][nt];
      if (!is_z){
        *(float2*)&g_xm[(size_t)row*512+col]     = make_float2(c[0],c[1]);
        *(float2*)&g_xm[(size_t)(row+8)*512+col] = make_float2(c[2],c[3]);
      } else {
        int cz = col-512;
        *(float2*)&g_zsil[(size_t)row*512+cz]     = make_float2(silu(c[0]),silu(c[1]));
        *(float2*)&g_zsil[(size_t)(row+8)*512+cz] = make_float2(silu(c[2]),silu(c[3]));
      }
    }
  }
}

// ---------------- causal conv1d as shifted GEMM + silu (pipelined) --------
__global__ __launch_bounds__(256) void k_conv(const float* __restrict__ convb){
  extern __shared__ float smdyn[];
  int bm = blockIdx.y*128, bn = blockIdx.x*128;
  const int tid=threadIdx.x, warp=tid>>5, lane=tid&31, gid=lane>>2, tig=lane&3;
  const int wm=(warp>>1)*32, wn=(warp&1)*64;
  const int m0=tid>>2, m1=m0+64, c0=(tid&3)*4;
  const int s0 = (bm+m0)&(S_-1), s1 = (bm+m1)&(S_-1);
  float acc[2][8][4];
  #pragma unroll
  for(int i=0;i<2;i++)for(int j=0;j<8;j++)for(int e=0;e<4;e++)acc[i][j][e]=0;
  const float* W = g_Wt + (size_t)bn*2048;
  float4 ra0 = (s0-3>=0) ? *(const float4*)&g_xm[(size_t)(bm+m0-3)*512 + c0] : make_float4(0,0,0,0);
  float4 ra1 = (s1-3>=0) ? *(const float4*)&g_xm[(size_t)(bm+m1-3)*512 + c0] : make_float4(0,0,0,0);
  float4 rb0 = *(const float4*)&W[(size_t)m0*2048 + c0];
  float4 rb1 = *(const float4*)&W[(size_t)m1*2048 + c0];
  int buf = 0;
  for (int k0=0;k0<2048;k0+=16){
    float* Ah = smdyn + buf*GSTAGE;
    float* Al = Ah + TILEF;
    float* Bh = Al + TILEF;
    float* Bl = Bh + TILEF;
    sp4(&Ah[m0*PADK+c0], &Al[m0*PADK+c0], ra0);
    sp4(&Ah[m1*PADK+c0], &Al[m1*PADK+c0], ra1);
    sp4(&Bh[m0*PADK+c0], &Bl[m0*PADK+c0], rb0);
    sp4(&Bh[m1*PADK+c0], &Bl[m1*PADK+c0], rb1);
    __syncthreads();
    int kn = k0+16;
    if (kn < 2048){
      int tap = kn>>9, i0 = kn&511;
      ra0 = (s0+tap-3>=0) ? *(const float4*)&g_xm[(size_t)(bm+m0+tap-3)*512 + i0 + c0]
                          : make_float4(0,0,0,0);
      ra1 = (s1+tap-3>=0) ? *(const float4*)&g_xm[(size_t)(bm+m1+tap-3)*512 + i0 + c0]
                          : make_float4(0,0,0,0);
      rb0 = *(const float4*)&W[(size_t)m0*2048 + kn + c0];
      rb1 = *(const float4*)&W[(size_t)m1*2048 + kn + c0];
    }
    mm_slice(Ah,Al,Bh,Bl, wm,wn,gid,tig, acc);
    buf ^= 1;
  }
  #pragma unroll
  for (int mt=0;mt<2;mt++){
    #pragma unroll
    for (int nt=0;nt<8;nt++){
      int row = bm+wm+mt*16+gid;
      int col = bn+wn+nt*8+tig*2;
      float b0 = convb[col], b1 = convb[col+1];
      float* c = acc[mt][nt];
      *(float2*)&g_xc[(size_t)row*512+col]     = make_float2(silu(c[0]+b0),silu(c[1]+b1));
      *(float2*)&g_xc[(size_t)(row+8)*512+col] = make_float2(silu(c[2]+b0),silu(c[3]+b1));
    }
  }
}

// ---------------- headwise q/k/v ----------------
__global__ __launch_bounds__(256) void k_qkv(const float* __restrict__ Wq,
                                             const float* __restrict__ Wk,
                                             const float* __restrict__ Wv){
  extern __shared__ float smdyn[];
  int zz = blockIdx.z; int op = zz>>2; int h = zz&3;
  const float* A  = (op==2 ? g_xm : g_xc) + h*128;
  const float* Wp = (op==0 ? Wq : (op==1 ? Wk : Wv)) + (size_t)h*128*128;
  float* Cp = (op==0 ? g_q : (op==1 ? g_k : g_v)) + h*128;
  int bm = blockIdx.y*128;
  float acc[2][8][4];
  #pragma unroll
  for(int i=0;i<2;i++)for(int j=0;j<8;j++)for(int e=0;e<4;e++)acc[i][j][e]=0;
  mm_core3p(A+(size_t)bm*512, 512, Wp, 128, 128, smdyn, acc);
  EPI_COORDS;
  #pragma unroll
  for (int mt=0;mt<2;mt++){
    #pragma unroll
    for (int nt=0;nt<8;nt++){
      int row = bm+wm+mt*16+gid;
      int col = wn+nt*8+tig*2;
      float* c = acc[mt][nt];
      *(float2*)&Cp[(size_t)row*512+col]     = make_float2(c[0],c[1]);
      *(float2*)&Cp[(size_t)(row+8)*512+col] = make_float2(c[2],c[3]);
    }
  }
}

// ---------------- down projection + bias ----------------
__global__ __launch_bounds__(256) void k_down(const float* __restrict__ Wd,
                                              const float* __restrict__ bd,
                                              float* __restrict__ out){
  extern __shared__ float smdyn[];
  int bm = blockIdx.y*128, bn = blockIdx.x*128;
  float acc[2][8][4];
  #pragma unroll
  for(int i=0;i<2;i++)for(int j=0;j<8;j++)for(int e=0;e<4;e++)acc[i][j][e]=0;
  mm_core3p(g_hs+(size_t)bm*512, 512, Wd+(size_t)bn*512, 512, 512, smdyn, acc);
  EPI_COORDS;
  #pragma unroll
  for (int mt=0;mt<2;mt++){
    #pragma unroll
    for (int nt=0;nt<8;nt++){
      int row = bm+wm+mt*16+gid;
      int col = bn+wn+nt*8+tig*2;
      float b0 = bd[col], b1 = bd[col+1];
      float* c = acc[mt][nt];
      *(float2*)&out[(size_t)row*512+col]     = make_float2(c[0]+b0,c[1]+b1);
      *(float2*)&out[(size_t)(row+8)*512+col] = make_float2(c[2]+b0,c[3]+b1);
    }
  }
}

// ---------------- gate projections ----------------
__global__ void k_gates(const float* __restrict__ Wi, const float* __restrict__ bi,
                        const float* __restrict__ Wf, const float* __restrict__ bf){
  int r = blockIdx.x; int tid = threadIdx.x;
  float pi[4]={0,0,0,0}, pf[4]={0,0,0,0};
  const float* qr = g_q + (size_t)r*512;
  const float* kr = g_k + (size_t)r*512;
  const float* vr = g_v + (size_t)r*512;
  for (int e=tid; e<512; e+=128){
    float a=qr[e], c=kr[e], d=vr[e];
    #pragma unroll
    for (int h=0;h<4;h++){
      const float* wih = Wi + h*1536; const float* wfh = Wf + h*1536;
      pi[h] += a*wih[e] + c*wih[512+e] + d*wih[1024+e];
      pf[h] += a*wfh[e] + c*wfh[512+e] + d*wfh[1024+e];
    }
  }
  __shared__ float red[8][128];
  #pragma unroll
  for (int h=0;h<4;h++){ red[h][tid]=pi[h]; red[4+h][tid]=pf[h]; }
  __syncthreads();
  for (int sft=64; sft>=1; sft>>=1){
    if (tid < sft){
      #pragma unroll
      for (int a=0;a<8;a++) red[a][tid]+=red[a][tid+sft];
    }
    __syncthreads();
  }
  if (tid < 4){
    int b = r>>11, s = r&2047;
    g_ig[((size_t)b*4+tid)*2048 + s] = red[tid][0]   + bi[tid];
    g_fg[((size_t)b*4+tid)*2048 + s] = red[4+tid][0] + bf[tid];
  }
}

// ---------------- per-(b,h) scan ----------------
__global__ void k_scan(){
  int bh = blockIdx.x; int t = threadIdx.x;
  const float* fg = g_fg + (size_t)bh*2048;
  const float* ig = g_ig + (size_t)bh*2048;
  double lcum[8]; double run = 0.0;
  #pragma unroll
  for (int u=0;u<8;u++){
    double x = (double)fg[t*8+u];
    double ls = (x < 0.0) ? (x - log1p(exp(x))) : (-log1p(exp(-x)));
    run += ls; lcum[u] = run;
  }
  __shared__ double sh[256];
  sh[t] = run; __syncthreads();
  for (int off=1; off<256; off<<=1){
    double cur = sh[t]; double oth = (t>=off)? sh[t-off] : 0.0;
    __syncthreads(); sh[t] = cur + oth; __syncthreads();
  }
  double base = (t>0)? sh[t-1] : 0.0;
  double dv[8], lf[8]; double runm = -1e300;
  #pragma unroll
  for (int u=0;u<8;u++){
    double lfc = base + lcum[u];
    lf[u] = lfc; dv[u] = (double)ig[t*8+u] - lfc;
    if (dv[u] > runm) runm = dv[u];
  }
  __syncthreads();
  sh[t] = runm; __syncthreads();
  for (int off=1; off<256; off<<=1){
    double cur = sh[t]; double oth = (t>=off)? sh[t-off] : -1e300;
    __syncthreads(); sh[t] = (cur>oth)?cur:oth; __syncthreads();
  }
  double basem = (t>0)? sh[t-1] : -1e300;
  double rm = basem;
  #pragma unroll
  for (int u=0;u<8;u++){
    if (dv[u] > rm) rm = dv[u];
    int j = bh*2048 + t*8 + u;
    g_dkey[j] = (float)dv[u];
    g_mrow[j] = (float)rm;
    g_mexp[j] = (float)exp(-(lf[u] + rm));
  }
}

// ---------------- 3xTF32 flash causal mLSTM attention (pipelined) ---------
#define OFF_QH   0
#define OFF_QL   (64*132)
#define OFF_BUF  (2*64*132)
#define BUF_SZ   (2*64*136)
#define OFF_SSH  (OFF_BUF + BUF_SZ)
#define OFF_SSL  (OFF_SSH + 64*68)
#define OFF_DK   (OFF_SSL + 64*68)
#define OFF_RED  (OFF_DK + 64)
#define OFF_SINV (OFF_RED + 128)
#define ATT_FLOATS (OFF_SINV + 64)
#define ATT_SMEM (ATT_FLOATS*4)

__global__ __launch_bounds__(256) void k_attn(){
  extern __shared__ float sm[];
  float* QH = sm + OFF_QH;
  float* QL = sm + OFF_QL;
  float* KH = sm + OFF_BUF;            // stride 132
  float* KL = KH + 64*132;
  float* VH = sm + OFF_BUF;            // stride 136 (aliases K region)
  float* VL = VH + 64*136;
  float* SSH = sm + OFF_SSH;
  float* SSL = sm + OFF_SSL;
  float* dks = sm + OFF_DK;
  float* red = sm + OFF_RED;
  float* sinv= sm + OFF_SINV;

  int bh = blockIdx.y; int b = bh>>2, h = bh&3;
  int it = (int)gridDim.x - 1 - (int)blockIdx.x;
  int i0 = it*64;
  const int tid=threadIdx.x, warp=tid>>5, lane=tid&31, gid=lane>>2, tig=lane&3;
  const int wr=warp>>1, wc=warp&1;
  const int qm = wr*16;
  const float scale = 0.08838834764831845f;
  const int lrow = tid>>5, lc4 = (tid&31)*4;

  const float* qbase = g_q + ((size_t)(b*2048 + i0))*512 + h*128;
  #pragma unroll
  for (int u=0;u<8;u++){
    int row = lrow + u*8;
    sp4(&QH[row*132+lc4], &QL[row*132+lc4], *(const float4*)&qbase[(size_t)row*512 + lc4]);
  }
  float mr0 = g_mrow[bh*2048 + i0 + qm + gid];
  float mr1 = g_mrow[bh*2048 + i0 + qm + gid + 8];

  float oacc[8][4];
  #pragma unroll
  for (int nt=0;nt<8;nt++){oacc[nt][0]=0;oacc[nt][1]=0;oacc[nt][2]=0;oacc[nt][3]=0;}
  float psum0 = 0.f, psum1 = 0.f;

  float4 kreg[8], vreg[8];
  {
    const float* kb = g_k + ((size_t)(b*2048))*512 + h*128;
    #pragma unroll
    for (int u=0;u<8;u++){
      int row = lrow + u*8;
      kreg[u] = *(const float4*)&kb[(size_t)row*512 + lc4];
    }
  }

  for (int j0 = 0; j0 <= i0; j0 += 64){
    __syncthreads();
    #pragma unroll
    for (int u=0;u<8;u++){
      int row = lrow + u*8;
      sp4(&KH[row*132+lc4], &KL[row*132+lc4], kreg[u]);
    }
    if (tid < 64) dks[tid] = g_dkey[bh*2048 + j0 + tid];
    __syncthreads();

    const float* vbase = g_v + ((size_t)(b*2048 + j0))*512 + h*128;
    #pragma unroll
    for (int u=0;u<8;u++){
      int row = lrow + u*8;
      vreg[u] = *(const float4*)&vbase[(size_t)row*512 + lc4];
    }

    float sacc[4][4];
    #pragma unroll
    for (int nt=0;nt<4;nt++){sacc[nt][0]=0;sacc[nt][1]=0;sacc[nt][2]=0;sacc[nt][3]=0;}
    #pragma unroll
    for (int kk=0;kk<128;kk+=8){
      unsigned ah[4], al[4];
      ah[0]=__float_as_uint(QH[(qm+gid  )*132 + kk+tig  ]);
      ah[1]=__float_as_uint(QH[(qm+gid+8)*132 + kk+tig  ]);
      ah[2]=__float_as_uint(QH[(qm+gid  )*132 + kk+tig+4]);
      ah[3]=__float_as_uint(QH[(qm+gid+8)*132 + kk+tig+4]);
      al[0]=__float_as_uint(QL[(qm+gid  )*132 + kk+tig  ]);
      al[1]=__float_as_uint(QL[(qm+gid+8)*132 + kk+tig  ]);
      al[2]=__float_as_uint(QL[(qm+gid  )*132 + kk+tig+4]);
      al[3]=__float_as_uint(QL[(qm+gid+8)*132 + kk+tig+4]);
      #pragma unroll
      for (int nt=0;nt<4;nt++){
        int jr = wc*32+nt*8+gid;
        unsigned bh2[2], bl2[2];
        bh2[0]=__float_as_uint(KH[jr*132 + kk+tig  ]);
        bh2[1]=__float_as_uint(KH[jr*132 + kk+tig+4]);
        bl2[0]=__float_as_uint(KL[jr*132 + kk+tig  ]);
        bl2[1]=__float_as_uint(KL[jr*132 + kk+tig+4]);
        mma8(sacc[nt], al, bh2);
        mma8(sacc[nt], ah, bl2);
        mma8(sacc[nt], ah, bh2);
      }
    }
    bool diag = (j0 == i0);
    #pragma unroll
    for (int nt=0;nt<4;nt++){
      int jl = wc*32+nt*8+tig*2;
      float d0 = dks[jl], d1 = dks[jl+1];
      int il0 = qm+gid, il1 = il0+8;
      float s00 = sacc[nt][0]*scale*__expf(d0 - mr0);
      float s01 = sacc[nt][1]*scale*__expf(d1 - mr0);
      float s10 = sacc[nt][2]*scale*__expf(d0 - mr1);
      float s11 = sacc[nt][3]*scale*__expf(d1 - mr1);
      if (diag){
        if (jl   > il0) s00 = 0.f;
        if (jl+1 > il0) s01 = 0.f;
        if (jl   > il1) s10 = 0.f;
        if (jl+1 > il1) s11 = 0.f;
      }
      psum0 += s00 + s01;
      psum1 += s10 + s11;
      float h00=tf32r(s00), h01=tf32r(s01), h10=tf32r(s10), h11=tf32r(s11);
      *(float2*)&SSH[il0*68 + jl] = make_float2(h00, h01);
      *(float2*)&SSH[il1*68 + jl] = make_float2(h10, h11);
      *(float2*)&SSL[il0*68 + jl] = make_float2(tf32r(s00-h00), tf32r(s01-h01));
      *(float2*)&SSL[il1*68 + jl] = make_float2(tf32r(s10-h10), tf32r(s11-h11));
    }
    __syncthreads();

    #pragma unroll
    for (int u=0;u<8;u++){
      int row = lrow + u*8;
      sp4(&VH[row*136+lc4], &VL[row*136+lc4], vreg[u]);
    }
    __syncthreads();

    if (j0 + 64 <= i0){
      const float* kb = g_k + ((size_t)(b*2048 + j0 + 64))*512 + h*128;
      #pragma unroll
      for (int u=0;u<8;u++){
        int row = lrow + u*8;
        kreg[u] = *(const float4*)&kb[(size_t)row*512 + lc4];
      }
    }

    #pragma unroll
    for (int kk=0;kk<64;kk+=8){
      unsigned ah[4], al[4];
      ah[0]=__float_as_uint(SSH[(qm+gid  )*68 + kk+tig  ]);
      ah[1]=__float_as_uint(SSH[(qm+gid+8)*68 + kk+tig  ]);
      ah[2]=__float_as_uint(SSH[(qm+gid  )*68 + kk+tig+4]);
      ah[3]=__float_as_uint(SSH[(qm+gid+8)*68 + kk+tig+4]);
      al[0]=__float_as_uint(SSL[(qm+gid  )*68 + kk+tig  ]);
      al[1]=__float_as_uint(SSL[(qm+gid+8)*68 + kk+tig  ]);
      al[2]=__float_as_uint(SSL[(qm+gid  )*68 + kk+tig+4]);
      al[3]=__float_as_uint(SSL[(qm+gid+8)*68 + kk+tig+4]);
      #pragma unroll
      for (int nt=0;nt<8;nt++){
        int dc = wc*64+nt*8+gid;
        unsigned bh2[2], bl2[2];
        bh2[0]=__float_as_uint(VH[(kk+tig  )*136 + dc]);
        bh2[1]=__float_as_uint(VH[(kk+tig+4)*136 + dc]);
        bl2[0]=__float_as_uint(VL[(kk+tig  )*136 + dc]);
        bl2[1]=__float_as_uint(VL[(kk+tig+4)*136 + dc]);
        mma8(oacc[nt], al, bh2);
        mma8(oacc[nt], ah, bl2);
        mma8(oacc[nt], ah, bh2);
      }
    }
  }

  psum0 += __shfl_xor_sync(0xffffffffu, psum0, 1);
  psum0 += __shfl_xor_sync(0xffffffffu, psum0, 2);
  psum1 += __shfl_xor_sync(0xffffffffu, psum1, 1);
  psum1 += __shfl_xor_sync(0xffffffffu, psum1, 2);
  if (tig == 0){
    red[(qm+gid)*2   + wc] = psum0;
    red[(qm+gid+8)*2 + wc] = psum1;
  }
  __syncthreads();
  if (tid < 64){
    float s2 = red[tid*2] + red[tid*2+1];
    float nrm = fmaxf(fabsf(s2), g_mexp[bh*2048 + i0 + tid]);
    sinv[tid] = 1.f/(nrm + 1e-6f);
  }
  __syncthreads();

  float iv0 = sinv[qm+gid], iv1 = sinv[qm+gid+8];
  float* obase = g_h + ((size_t)(b*2048 + i0))*512 + h*128;
  #pragma unroll
  for (int nt=0;nt<8;nt++){
    int col = wc*64+nt*8+tig*2;
    *(float2*)&obase[(size_t)(qm+gid)*512 + col] =
      make_float2(oacc[nt][0]*iv0, oacc[nt][1]*iv0);
    *(float2*)&obase[(size_t)(qm+gid+8)*512 + col] =
      make_float2(oacc[nt][2]*iv1, oacc[nt][3]*iv1);
  }
}

// ---------------- groupnorm + skip + z-gate ----------------
__global__ void k_norm(const float* __restrict__ skip){
  int r = blockIdx.x; int t = threadIdx.x;
  float v[4];
  #pragma unroll
  for (int h=0;h<4;h++) v[h] = g_h[(size_t)r*512 + h*128 + t];
  __shared__ float rs[4][128], rq[4][128];
  #pragma unroll
  for (int h=0;h<4;h++){ rs[h][t]=v[h]; rq[h][t]=v[h]*v[h]; }
  __syncthreads();
  for (int sft=64; sft>=1; sft>>=1){
    if (t < sft){
      #pragma unroll
      for (int h=0;h<4;h++){ rs[h][t]+=rs[h][t+sft]; rq[h][t]+=rq[h][t+sft]; }
    }
    __syncthreads();
  }
  #pragma unroll
  for (int h=0;h<4;h++){
    float mean = rs[h][0]*(1.f/128.f);
    float var  = rq[h][0]*(1.f/128.f) - mean*mean;
    float hn = (v[h]-mean)*rsqrtf(var + 1e-5f);
    int e = h*128 + t;
    float hskip = hn + skip[e]*g_xc[(size_t)r*512 + e];
    g_hs[(size_t)r*512 + e] = hskip * g_zsil[(size_t)r*512 + e];
  }
}

// ---------------- launch ----------------
extern "C" void kernel_launch(void* const* d_in, const int* in_sizes, int n_in,
                              void* d_out, int out_size){
  const float* x      = (const float*)d_in[0];
  const float* W_up   = (const float*)d_in[1];
  const float* Wq     = (const float*)d_in[2];
  const float* Wk     = (const float*)d_in[3];
  const float* Wv     = (const float*)d_in[4];
  const float* conv_w = (const float*)d_in[5];
  const float* conv_b = (const float*)d_in[6];
  const float* Wi     = (const float*)d_in[7];
  const float* bi     = (const float*)d_in[8];
  const float* Wf     = (const float*)d_in[9];
  const float* bf     = (const float*)d_in[10];
  const float* skip   = (const float*)d_in[11];
  const float* W_down = (const float*)d_in[12];
  const float* b_down = (const float*)d_in[13];
  float* out = (float*)d_out;

  cudaFuncSetAttribute(k_attn, cudaFuncAttributeMaxDynamicSharedMemorySize, ATT_SMEM);
  cudaFuncSetAttribute(k_up,   cudaFuncAttributeMaxDynamicSharedMemorySize, GEMM_SMEM);
  cudaFuncSetAttribute(k_conv, cudaFuncAttributeMaxDynamicSharedMemorySize, GEMM_SMEM);
  cudaFuncSetAttribute(k_qkv,  cudaFuncAttributeMaxDynamicSharedMemorySize, GEMM_SMEM);
  cudaFuncSetAttribute(k_down, cudaFuncAttributeMaxDynamicSharedMemorySize, GEMM_SMEM);

  k_wt  <<<512, 512>>>(conv_w);
  k_up  <<<dim3(8,32), 256, GEMM_SMEM>>>(x, W_up);
  k_conv<<<dim3(4,32), 256, GEMM_SMEM>>>(conv_b);
  k_qkv <<<dim3(1,32,12), 256, GEMM_SMEM>>>(Wq, Wk, Wv);
  k_gates<<<4096,128>>>(Wi, bi, Wf, bf);
  k_scan<<<8,256>>>();
  k_attn<<<dim3(32,8),256, ATT_SMEM>>>();
  k_norm<<<4096,128>>>(skip);
  k_down<<<dim3(4,32),256, GEMM_SMEM>>>(W_down, b_down, out);
}

// round 14
// speedup vs baseline: 2.3499x; 1.2460x over previous
#include <cuda_runtime.h>
#include <cuda_bf16.h>
#include <math.h>

#define B_  2
#define S_  2048
#define E_  512
#define NH_ 4
#define DH_ 128
#define R_  (B_*S_)

// ------------------------- device scratch -------------------------
__device__ float g_xm  [R_*E_];
__device__ float g_zsil[R_*E_];
__device__ float g_xc  [R_*E_];
__device__ float g_q   [R_*E_];
__device__ float g_k   [R_*E_];
__device__ float g_v   [R_*E_];
__device__ float g_h   [R_*E_];
__device__ float g_hs  [R_*E_];
__device__ float g_Wt  [E_*4*E_];          // [o][tap*512+i]
__device__ float g_ig  [B_*NH_*S_];
__device__ float g_fg  [B_*NH_*S_];
__device__ float g_dkey[B_*NH_*S_];
__device__ float g_mrow[B_*NH_*S_];
__device__ float g_mexp[B_*NH_*S_];

// ------------------------- helpers -------------------------
__device__ __forceinline__ void mma16(float c[4], const unsigned a[4], const unsigned b[2]){
  asm volatile("mma.sync.aligned.m16n8k16.row.col.f32.bf16.bf16.f32 "
    "{%0,%1,%2,%3}, {%4,%5,%6,%7}, {%8,%9}, {%0,%1,%2,%3};"
    : "+f"(c[0]),"+f"(c[1]),"+f"(c[2]),"+f"(c[3])
    : "r"(a[0]),"r"(a[1]),"r"(a[2]),"r"(a[3]), "r"(b[0]),"r"(b[1]));
}
__device__ __forceinline__ float silu(float x){ return x/(1.f+__expf(-x)); }
__device__ __forceinline__ unsigned pkb(__nv_bfloat16 lo, __nv_bfloat16 hi){
  return ((unsigned)__bfloat16_as_ushort(hi)<<16) | (unsigned)__bfloat16_as_ushort(lo);
}
// split float4 (4 consecutive k) into 2 hi words + 2 lo words (bf16x2)
__device__ __forceinline__ void spb4(unsigned hw[2], unsigned lw[2], float4 v){
  __nv_bfloat16 h0=__float2bfloat16_rn(v.x), h1=__float2bfloat16_rn(v.y),
                h2=__float2bfloat16_rn(v.z), h3=__float2bfloat16_rn(v.w);
  float l0=v.x-__bfloat162float(h0), l1=v.y-__bfloat162float(h1),
        l2=v.z-__bfloat162float(h2), l3=v.w-__bfloat162float(h3);
  hw[0]=pkb(h0,h1); hw[1]=pkb(h2,h3);
  lw[0]=pkb(__float2bfloat16_rn(l0),__float2bfloat16_rn(l1));
  lw[1]=pkb(__float2bfloat16_rn(l2),__float2bfloat16_rn(l3));
}

// ---------------- conv weight repack: Wt[o][tap*512+i] ----------------
__global__ void k_wt(const float* __restrict__ conv_w){
  int o = blockIdx.x; int i = threadIdx.x;
  #pragma unroll
  for (int tap=0;tap<4;tap++)
    g_Wt[(size_t)o*2048 + tap*512 + i] = conv_w[((size_t)o*512+i)*4 + tap];
}

// ---------------- pipelined split-BF16 mma GEMM core ----------------
// C[128,128]: A[128,K], W[128 N-rows, K] row-major. 256 thr, 8 warps 4x2,
// warp tile 32x64; 2-stage smem double buffer; bf16 tiles 12 words/row.
#define WPR 12                   // 32-bit words per tile row (16 bf16 + pad)
#define TW  (128*WPR)            // words per tile
#define GST (4*TW)               // Ah,Al,Bh,Bl per stage
#define GEMM_SMEM (2*GST*4)      // 49152 bytes

__device__ __forceinline__ void mm_slice_bf(
    const unsigned* Ah, const unsigned* Al, const unsigned* Bh, const unsigned* Bl,
    int wm, int wn, int gid, int tig, float acc[2][8][4])
{
  unsigned ua[2][4], la[2][4];
  #pragma unroll
  for (int mt=0;mt<2;mt++){
    int r = wm+mt*16+gid;
    ua[mt][0]=Ah[(r  )*WPR+tig];   ua[mt][1]=Ah[(r+8)*WPR+tig];
    ua[mt][2]=Ah[(r  )*WPR+4+tig]; ua[mt][3]=Ah[(r+8)*WPR+4+tig];
    la[mt][0]=Al[(r  )*WPR+tig];   la[mt][1]=Al[(r+8)*WPR+tig];
    la[mt][2]=Al[(r  )*WPR+4+tig]; la[mt][3]=Al[(r+8)*WPR+4+tig];
  }
  #pragma unroll
  for (int nt=0;nt<8;nt++){
    int cc = wn+nt*8+gid;
    unsigned ub[2], lb[2];
    ub[0]=Bh[cc*WPR+tig]; ub[1]=Bh[cc*WPR+4+tig];
    lb[0]=Bl[cc*WPR+tig]; lb[1]=Bl[cc*WPR+4+tig];
    #pragma unroll
    for (int mt=0;mt<2;mt++){
      mma16(acc[mt][nt], la[mt], ub);
      mma16(acc[mt][nt], ua[mt], lb);
      mma16(acc[mt][nt], ua[mt], ub);
    }
  }
}

__device__ __forceinline__ void mm_core_bf(
    const float* __restrict__ A, int lda,
    const float* __restrict__ W, int ldw, int K,
    unsigned* __restrict__ smw, float acc[2][8][4])
{
  const int tid=threadIdx.x, warp=tid>>5, lane=tid&31, gid=lane>>2, tig=lane&3;
  const int wm=(warp>>1)*32, wn=(warp&1)*64;
  const int m0=tid>>2, m1=m0+64, c0=(tid&3)*4, w0=c0>>1;
  float4 ra0 = *(const float4*)&A[(size_t)m0*lda + c0];
  float4 ra1 = *(const float4*)&A[(size_t)m1*lda + c0];
  float4 rb0 = *(const float4*)&W[(size_t)m0*ldw + c0];
  float4 rb1 = *(const float4*)&W[(size_t)m1*ldw + c0];
  int buf = 0;
  for (int k0=0;k0<K;k0+=16){
    unsigned* Ah = smw + buf*GST;
    unsigned* Al = Ah + TW;
    unsigned* Bh = Al + TW;
    unsigned* Bl = Bh + TW;
    unsigned hw[2], lw[2];
    spb4(hw,lw,ra0); Ah[m0*WPR+w0]=hw[0]; Ah[m0*WPR+w0+1]=hw[1]; Al[m0*WPR+w0]=lw[0]; Al[m0*WPR+w0+1]=lw[1];
    spb4(hw,lw,ra1); Ah[m1*WPR+w0]=hw[0]; Ah[m1*WPR+w0+1]=hw[1]; Al[m1*WPR+w0]=lw[0]; Al[m1*WPR+w0+1]=lw[1];
    spb4(hw,lw,rb0); Bh[m0*WPR+w0]=hw[0]; Bh[m0*WPR+w0+1]=hw[1]; Bl[m0*WPR+w0]=lw[0]; Bl[m0*WPR+w0+1]=lw[1];
    spb4(hw,lw,rb1); Bh[m1*WPR+w0]=hw[0]; Bh[m1*WPR+w0+1]=hw[1]; Bl[m1*WPR+w0]=lw[0]; Bl[m1*WPR+w0+1]=lw[1];
    __syncthreads();
    if (k0+16 < K){
      ra0 = *(const float4*)&A[(size_t)m0*lda + k0+16 + c0];
      ra1 = *(const float4*)&A[(size_t)m1*lda + k0+16 + c0];
      rb0 = *(const float4*)&W[(size_t)m0*ldw + k0+16 + c0];
      rb1 = *(const float4*)&W[(size_t)m1*ldw + k0+16 + c0];
    }
    mm_slice_bf(Ah,Al,Bh,Bl, wm,wn,gid,tig, acc);
    __syncthreads();
    buf ^= 1;
  }
}

#define EPI_COORDS \
  const int tid=threadIdx.x, warp=tid>>5, lane=tid&31, gid=lane>>2, tig=lane&3; \
  const int wm=(warp>>1)*32, wn=(warp&1)*64; (void)wm; (void)tid;

// ---------------- up projection ----------------
__global__ __launch_bounds__(256,2) void k_up(const float* __restrict__ X,
                                              const float* __restrict__ Wup){
  extern __shared__ unsigned smw[];
  int bm = blockIdx.y*128, bn = blockIdx.x*128;
  float acc[2][8][4];
  #pragma unroll
  for(int i=0;i<2;i++)for(int j=0;j<8;j++)for(int e=0;e<4;e++)acc[i][j][e]=0;
  mm_core_bf(X+(size_t)bm*512, 512, Wup+(size_t)bn*512, 512, 512, smw, acc);
  EPI_COORDS;
  bool is_z = (bn >= 512);
  #pragma unroll
  for (int mt=0;mt<2;mt++){
    #pragma unroll
    for (int nt=0;nt<8;nt++){
      int row = bm+wm+mt*16+gid;
      int col = bn+wn+nt*8+tig*2;
      float* c = acc[mt][nt];
      if (!is_z){
        *(float2*)&g_xm[(size_t)row*512+col]     = make_float2(c[0],c[1]);
        *(float2*)&g_xm[(size_t)(row+8)*512+col] = make_float2(c[2],c[3]);
      } else {
        int cz = col-512;
        *(float2*)&g_zsil[(size_t)row*512+cz]     = make_float2(silu(c[0]),silu(c[1]));
        *(float2*)&g_zsil[(size_t)(row+8)*512+cz] = make_float2(silu(c[2]),silu(c[3]));
      }
    }
  }
}

// ---------------- causal conv1d as shifted GEMM + silu ----------------
__global__ __launch_bounds__(256,2) void k_conv(const float* __restrict__ convb){
  extern __shared__ unsigned smw[];
  int bm = blockIdx.y*128, bn = blockIdx.x*128;
  const int tid=threadIdx.x, warp=tid>>5, lane=tid&31, gid=lane>>2, tig=lane&3;
  const int wm=(warp>>1)*32, wn=(warp&1)*64;
  const int m0=tid>>2, m1=m0+64, c0=(tid&3)*4, w0=c0>>1;
  const int s0 = (bm+m0)&(S_-1), s1 = (bm+m1)&(S_-1);
  float acc[2][8][4];
  #pragma unroll
  for(int i=0;i<2;i++)for(int j=0;j<8;j++)for(int e=0;e<4;e++)acc[i][j][e]=0;
  const float* W = g_Wt + (size_t)bn*2048;
  float4 ra0 = (s0-3>=0) ? *(const float4*)&g_xm[(size_t)(bm+m0-3)*512 + c0] : make_float4(0,0,0,0);
  float4 ra1 = (s1-3>=0) ? *(const float4*)&g_xm[(size_t)(bm+m1-3)*512 + c0] : make_float4(0,0,0,0);
  float4 rb0 = *(const float4*)&W[(size_t)m0*2048 + c0];
  float4 rb1 = *(const float4*)&W[(size_t)m1*2048 + c0];
  int buf = 0;
  for (int k0=0;k0<2048;k0+=16){
    unsigned* Ah = smw + buf*GST;
    unsigned* Al = Ah + TW;
    unsigned* Bh = Al + TW;
    unsigned* Bl = Bh + TW;
    unsigned hw[2], lw[2];
    spb4(hw,lw,ra0); Ah[m0*WPR+w0]=hw[0]; Ah[m0*WPR+w0+1]=hw[1]; Al[m0*WPR+w0]=lw[0]; Al[m0*WPR+w0+1]=lw[1];
    spb4(hw,lw,ra1); Ah[m1*WPR+w0]=hw[0]; Ah[m1*WPR+w0+1]=hw[1]; Al[m1*WPR+w0]=lw[0]; Al[m1*WPR+w0+1]=lw[1];
    spb4(hw,lw,rb0); Bh[m0*WPR+w0]=hw[0]; Bh[m0*WPR+w0+1]=hw[1]; Bl[m0*WPR+w0]=lw[0]; Bl[m0*WPR+w0+1]=lw[1];
    spb4(hw,lw,rb1); Bh[m1*WPR+w0]=hw[0]; Bh[m1*WPR+w0+1]=hw[1]; Bl[m1*WPR+w0]=lw[0]; Bl[m1*WPR+w0+1]=lw[1];
    __syncthreads();
    int kn = k0+16;
    if (kn < 2048){
      int tap = kn>>9, i0 = kn&511;
      ra0 = (s0+tap-3>=0) ? *(const float4*)&g_xm[(size_t)(bm+m0+tap-3)*512 + i0 + c0]
                          : make_float4(0,0,0,0);
      ra1 = (s1+tap-3>=0) ? *(const float4*)&g_xm[(size_t)(bm+m1+tap-3)*512 + i0 + c0]
                          : make_float4(0,0,0,0);
      rb0 = *(const float4*)&W[(size_t)m0*2048 + kn + c0];
      rb1 = *(const float4*)&W[(size_t)m1*2048 + kn + c0];
    }
    mm_slice_bf(Ah,Al,Bh,Bl, wm,wn,gid,tig, acc);
    __syncthreads();
    buf ^= 1;
  }
  #pragma unroll
  for (int mt=0;mt<2;mt++){
    #pragma unroll
    for (int nt=0;nt<8;nt++){
      int row = bm+wm+mt*16+gid;
      int col = bn+wn+nt*8+tig*2;
      float b0 = convb[col], b1 = convb[col+1];
      float* c = acc[mt][nt];
      *(float2*)&g_xc[(size_t)row*512+col]     = make_float2(silu(c[0]+b0),silu(c[1]+b1));
      *(float2*)&g_xc[(size_t)(row+8)*512+col] = make_float2(silu(c[2]+b0),silu(c[3]+b1));
    }
  }
}

// ---------------- headwise q/k/v ----------------
__global__ __launch_bounds__(256,2) void k_qkv(const float* __restrict__ Wq,
                                               const float* __restrict__ Wk,
                                               const float* __restrict__ Wv){
  extern __shared__ unsigned smw[];
  int zz = blockIdx.z; int op = zz>>2; int h = zz&3;
  const float* A  = (op==2 ? g_xm : g_xc) + h*128;
  const float* Wp = (op==0 ? Wq : (op==1 ? Wk : Wv)) + (size_t)h*128*128;
  float* Cp = (op==0 ? g_q : (op==1 ? g_k : g_v)) + h*128;
  int bm = blockIdx.y*128;
  float acc[2][8][4];
  #pragma unroll
  for(int i=0;i<2;i++)for(int j=0;j<8;j++)for(int e=0;e<4;e++)acc[i][j][e]=0;
  mm_core_bf(A+(size_t)bm*512, 512, Wp, 128, 128, smw, acc);
  EPI_COORDS;
  #pragma unroll
  for (int mt=0;mt<2;mt++){
    #pragma unroll
    for (int nt=0;nt<8;nt++){
      int row = bm+wm+mt*16+gid;
      int col = wn+nt*8+tig*2;
      float* c = acc[mt][nt];
      *(float2*)&Cp[(size_t)row*512+col]     = make_float2(c[0],c[1]);
      *(float2*)&Cp[(size_t)(row+8)*512+col] = make_float2(c[2],c[3]);
    }
  }
}

// ---------------- down projection + bias ----------------
__global__ __launch_bounds__(256,2) void k_down(const float* __restrict__ Wd,
                                                const float* __restrict__ bd,
                                                float* __restrict__ out){
  extern __shared__ unsigned smw[];
  int bm = blockIdx.y*128, bn = blockIdx.x*128;
  float acc[2][8][4];
  #pragma unroll
  for(int i=0;i<2;i++)for(int j=0;j<8;j++)for(int e=0;e<4;e++)acc[i][j][e]=0;
  mm_core_bf(g_hs+(size_t)bm*512, 512, Wd+(size_t)bn*512, 512, 512, smw, acc);
  EPI_COORDS;
  #pragma unroll
  for (int mt=0;mt<2;mt++){
    #pragma unroll
    for (int nt=0;nt<8;nt++){
      int row = bm+wm+mt*16+gid;
      int col = bn+wn+nt*8+tig*2;
      float b0 = bd[col], b1 = bd[col+1];
      float* c = acc[mt][nt];
      *(float2*)&out[(size_t)row*512+col]     = make_float2(c[0]+b0,c[1]+b1);
      *(float2*)&out[(size_t)(row+8)*512+col] = make_float2(c[2]+b0,c[3]+b1);
    }
  }
}

// ---------------- gate projections ----------------
__global__ void k_gates(const float* __restrict__ Wi, const float* __restrict__ bi,
                        const float* __restrict__ Wf, const float* __restrict__ bf){
  int r = blockIdx.x; int tid = threadIdx.x;
  float pi[4]={0,0,0,0}, pf[4]={0,0,0,0};
  const float* qr = g_q + (size_t)r*512;
  const float* kr = g_k + (size_t)r*512;
  const float* vr = g_v + (size_t)r*512;
  for (int e=tid; e<512; e+=128){
    float a=qr[e], c=kr[e], d=vr[e];
    #pragma unroll
    for (int h=0;h<4;h++){
      const float* wih = Wi + h*1536; const float* wfh = Wf + h*1536;
      pi[h] += a*wih[e] + c*wih[512+e] + d*wih[1024+e];
      pf[h] += a*wfh[e] + c*wfh[512+e] + d*wfh[1024+e];
    }
  }
  __shared__ float red[8][128];
  #pragma unroll
  for (int h=0;h<4;h++){ red[h][tid]=pi[h]; red[4+h][tid]=pf[h]; }
  __syncthreads();
  for (int sft=64; sft>=1; sft>>=1){
    if (tid < sft){
      #pragma unroll
      for (int a=0;a<8;a++) red[a][tid]+=red[a][tid+sft];
    }
    __syncthreads();
  }
  if (tid < 4){
    int b = r>>11, s = r&2047;
    g_ig[((size_t)b*4+tid)*2048 + s] = red[tid][0]   + bi[tid];
    g_fg[((size_t)b*4+tid)*2048 + s] = red[4+tid][0] + bf[tid];
  }
}

// ---------------- per-(b,h) scan ----------------
__global__ void k_scan(){
  int bh = blockIdx.x; int t = threadIdx.x;
  const float* fg = g_fg + (size_t)bh*2048;
  const float* ig = g_ig + (size_t)bh*2048;
  double lcum[8]; double run = 0.0;
  #pragma unroll
  for (int u=0;u<8;u++){
    double x = (double)fg[t*8+u];
    double ls = (x < 0.0) ? (x - log1p(exp(x))) : (-log1p(exp(-x)));
    run += ls; lcum[u] = run;
  }
  __shared__ double sh[256];
  sh[t] = run; __syncthreads();
  for (int off=1; off<256; off<<=1){
    double cur = sh[t]; double oth = (t>=off)? sh[t-off] : 0.0;
    __syncthreads(); sh[t] = cur + oth; __syncthreads();
  }
  double base = (t>0)? sh[t-1] : 0.0;
  double dv[8], lf[8]; double runm = -1e300;
  #pragma unroll
  for (int u=0;u<8;u++){
    double lfc = base + lcum[u];
    lf[u] = lfc; dv[u] = (double)ig[t*8+u] - lfc;
    if (dv[u] > runm) runm = dv[u];
  }
  __syncthreads();
  sh[t] = runm; __syncthreads();
  for (int off=1; off<256; off<<=1){
    double cur = sh[t]; double oth = (t>=off)? sh[t-off] : -1e300;
    __syncthreads(); sh[t] = (cur>oth)?cur:oth; __syncthreads();
  }
  double basem = (t>0)? sh[t-1] : -1e300;
  double rm = basem;
  #pragma unroll
  for (int u=0;u<8;u++){
    if (dv[u] > rm) rm = dv[u];
    int j = bh*2048 + t*8 + u;
    g_dkey[j] = (float)dv[u];
    g_mrow[j] = (float)rm;
    g_mexp[j] = (float)exp(-(lf[u] + rm));
  }
}

// ---------------- split-BF16 flash causal mLSTM attention ----------------
// word offsets (unsigned units):
#define WQROW 68                 // Q/K tile row stride in words (136 bf16)
#define WSROW 36                 // S / Vt row stride in words
#define WQH   0
#define WQL   (WQH + 64*WQROW)
#define WBUF  (WQL + 64*WQROW)            // K hi/lo (2*64*68) or Vt hi/lo (2*128*36)
#define WBUFSZ (2*128*WSROW)              // 9216 words (Vt is larger)
#define WSSH  (WBUF + WBUFSZ)
#define WSSL  (WSSH + 64*WSROW)
#define WDK   (WSSL + 64*WSROW)
#define WRED  (WDK + 64)
#define WSINV (WRED + 128)
#define ATT_WORDS (WSINV + 64)
#define ATT_SMEM (ATT_WORDS*4)

__global__ __launch_bounds__(256) void k_attn(){
  extern __shared__ unsigned smu[];
  unsigned* QH = smu + WQH;
  unsigned* QL = smu + WQL;
  unsigned* KH = smu + WBUF;               // [64][68]
  unsigned* KL = KH + 64*WQROW;
  unsigned* VtH = smu + WBUF;              // [128][36] (aliases K region)
  unsigned* VtL = VtH + 128*WSROW;
  unsigned* SSH = smu + WSSH;              // [64][36]
  unsigned* SSL = smu + WSSL;
  float* dks = (float*)(smu + WDK);
  float* red = (float*)(smu + WRED);
  float* sinv= (float*)(smu + WSINV);

  int bh = blockIdx.y; int b = bh>>2, h = bh&3;
  int it = (int)gridDim.x - 1 - (int)blockIdx.x;
  int i0 = it*64;
  const int tid=threadIdx.x, warp=tid>>5, lane=tid&31, gid=lane>>2, tig=lane&3;
  const int wr=warp>>1, wc=warp&1;
  const int qm = wr*16;
  const float scale = 0.08838834764831845f;
  const int lrow = tid>>5, lc4 = (tid&31)*4, lw0 = (tid&31)*2;
  const int jp = tid&31, db = (tid>>5)*16;    // V-transpose mapping

  // load + split Q tile
  const float* qbase = g_q + ((size_t)(b*2048 + i0))*512 + h*128;
  #pragma unroll
  for (int u=0;u<8;u++){
    int row = lrow + u*8;
    unsigned hw[2], lw[2];
    spb4(hw,lw, *(const float4*)&qbase[(size_t)row*512 + lc4]);
    QH[row*WQROW + lw0] = hw[0]; QH[row*WQROW + lw0+1] = hw[1];
    QL[row*WQROW + lw0] = lw[0]; QL[row*WQROW + lw0+1] = lw[1];
  }
  float mr0 = g_mrow[bh*2048 + i0 + qm + gid];
  float mr1 = g_mrow[bh*2048 + i0 + qm + gid + 8];

  float oacc[8][4];
  #pragma unroll
  for (int nt=0;nt<8;nt++){oacc[nt][0]=0;oacc[nt][1]=0;oacc[nt][2]=0;oacc[nt][3]=0;}
  float psum0 = 0.f, psum1 = 0.f;

  float4 kreg[8], vreg[8];
  {
    const float* kb = g_k + ((size_t)(b*2048))*512 + h*128;
    #pragma unroll
    for (int u=0;u<8;u++){
      int row = lrow + u*8;
      kreg[u] = *(const float4*)&kb[(size_t)row*512 + lc4];
    }
  }

  for (int j0 = 0; j0 <= i0; j0 += 64){
    __syncthreads();
    #pragma unroll
    for (int u=0;u<8;u++){
      int row = lrow + u*8;
      unsigned hw[2], lw[2];
      spb4(hw,lw, kreg[u]);
      KH[row*WQROW + lw0] = hw[0]; KH[row*WQROW + lw0+1] = hw[1];
      KL[row*WQROW + lw0] = lw[0]; KL[row*WQROW + lw0+1] = lw[1];
    }
    if (tid < 64) dks[tid] = g_dkey[bh*2048 + j0 + tid];
    __syncthreads();

    // prefetch V (j-pair layout): rows 2jp, 2jp+1, d chunk db..db+15
    {
      const float* vb = g_v + ((size_t)(b*2048 + j0))*512 + h*128;
      #pragma unroll
      for (int u=0;u<4;u++){
        vreg[u]   = *(const float4*)&vb[(size_t)(2*jp  )*512 + db + u*4];
        vreg[u+4] = *(const float4*)&vb[(size_t)(2*jp+1)*512 + db + u*4];
      }
    }

    // QK^T: warp rows qm..qm+15, key cols wc*32..+31 ; k = 128 d, step 16
    float sacc[4][4];
    #pragma unroll
    for (int nt=0;nt<4;nt++){sacc[nt][0]=0;sacc[nt][1]=0;sacc[nt][2]=0;sacc[nt][3]=0;}
    #pragma unroll
    for (int kk=0;kk<128;kk+=16){
      int w = (kk>>1) + tig;
      unsigned ua[4], la[4];
      ua[0]=QH[(qm+gid  )*WQROW + w];   ua[1]=QH[(qm+gid+8)*WQROW + w];
      ua[2]=QH[(qm+gid  )*WQROW + w+4]; ua[3]=QH[(qm+gid+8)*WQROW + w+4];
      la[0]=QL[(qm+gid  )*WQROW + w];   la[1]=QL[(qm+gid+8)*WQROW + w];
      la[2]=QL[(qm+gid  )*WQROW + w+4]; la[3]=QL[(qm+gid+8)*WQROW + w+4];
      #pragma unroll
      for (int nt=0;nt<4;nt++){
        int jr = wc*32+nt*8+gid;
        unsigned ub[2], lb[2];
        ub[0]=KH[jr*WQROW + w]; ub[1]=KH[jr*WQROW + w+4];
        lb[0]=KL[jr*WQROW + w]; lb[1]=KL[jr*WQROW + w+4];
        mma16(sacc[nt], la, ub);
        mma16(sacc[nt], ua, lb);
        mma16(sacc[nt], ua, ub);
      }
    }
    bool diag = (j0 == i0);
    #pragma unroll
    for (int nt=0;nt<4;nt++){
      int jl = wc*32+nt*8+tig*2;
      float d0 = dks[jl], d1 = dks[jl+1];
      int il0 = qm+gid, il1 = il0+8;
      float s00 = sacc[nt][0]*scale*__expf(d0 - mr0);
      float s01 = sacc[nt][1]*scale*__expf(d1 - mr0);
      float s10 = sacc[nt][2]*scale*__expf(d0 - mr1);
      float s11 = sacc[nt][3]*scale*__expf(d1 - mr1);
      if (diag){
        if (jl   > il0) s00 = 0.f;
        if (jl+1 > il0) s01 = 0.f;
        if (jl   > il1) s10 = 0.f;
        if (jl+1 > il1) s11 = 0.f;
      }
      psum0 += s00 + s01;
      psum1 += s10 + s11;
      int jw = jl>>1;
      __nv_bfloat16 h00=__float2bfloat16_rn(s00), h01=__float2bfloat16_rn(s01),
                    h10=__float2bfloat16_rn(s10), h11=__float2bfloat16_rn(s11);
      SSH[il0*WSROW + jw] = pkb(h00,h01);
      SSH[il1*WSROW + jw] = pkb(h10,h11);
      SSL[il0*WSROW + jw] = pkb(__float2bfloat16_rn(s00-__bfloat162float(h00)),
                                __float2bfloat16_rn(s01-__bfloat162float(h01)));
      SSL[il1*WSROW + jw] = pkb(__float2bfloat16_rn(s10-__bfloat162float(h10)),
                                __float2bfloat16_rn(s11-__bfloat162float(h11)));
    }
    __syncthreads();                 // K consumed, S ready

    // store V transposed with j-pairs packed: word [d][jp] = (v[2jp][d], v[2jp+1][d])
    #pragma unroll
    for (int u=0;u<4;u++){
      const float* f0 = (const float*)&vreg[u];
      const float* f1 = (const float*)&vreg[u+4];
      #pragma unroll
      for (int cix=0;cix<4;cix++){
        int d = db + u*4 + cix;
        __nv_bfloat16 ha=__float2bfloat16_rn(f0[cix]), hb=__float2bfloat16_rn(f1[cix]);
        VtH[d*WSROW + jp] = pkb(ha,hb);
        VtL[d*WSROW + jp] = pkb(__float2bfloat16_rn(f0[cix]-__bfloat162float(ha)),
                                __float2bfloat16_rn(f1[cix]-__bfloat162float(hb)));
      }
    }
    __syncthreads();

    // prefetch next K tile
    if (j0 + 64 <= i0){
      const float* kb = g_k + ((size_t)(b*2048 + j0 + 64))*512 + h*128;
      #pragma unroll
      for (int u=0;u<8;u++){
        int row = lrow + u*8;
        kreg[u] = *(const float4*)&kb[(size_t)row*512 + lc4];
      }
    }

    // S @ V: rows qm..qm+15, d cols wc*64..+63 ; k = 64 j, step 16
    #pragma unroll
    for (int kk=0;kk<64;kk+=16){
      int w = (kk>>1) + tig;
      unsigned ua[4], la[4];
      ua[0]=SSH[(qm+gid  )*WSROW + w];   ua[1]=SSH[(qm+gid+8)*WSROW + w];
      ua[2]=SSH[(qm+gid  )*WSROW + w+4]; ua[3]=SSH[(qm+gid+8)*WSROW + w+4];
      la[0]=SSL[(qm+gid  )*WSROW + w];   la[1]=SSL[(qm+gid+8)*WSROW + w];
      la[2]=SSL[(qm+gid  )*WSROW + w+4]; la[3]=SSL[(qm+gid+8)*WSROW + w+4];
      #pragma unroll
      for (int nt=0;nt<8;nt++){
        int dc = wc*64+nt*8+gid;
        unsigned ub[2], lb[2];
        ub[0]=VtH[dc*WSROW + w]; ub[1]=VtH[dc*WSROW + w+4];
        lb[0]=VtL[dc*WSROW + w]; lb[1]=VtL[dc*WSROW + w+4];
        mma16(oacc[nt], la, ub);
        mma16(oacc[nt], ua, lb);
        mma16(oacc[nt], ua, ub);
      }
    }
  }

  psum0 += __shfl_xor_sync(0xffffffffu, psum0, 1);
  psum0 += __shfl_xor_sync(0xffffffffu, psum0, 2);
  psum1 += __shfl_xor_sync(0xffffffffu, psum1, 1);
  psum1 += __shfl_xor_sync(0xffffffffu, psum1, 2);
  if (tig == 0){
    red[(qm+gid)*2   + wc] = psum0;
    red[(qm+gid+8)*2 + wc] = psum1;
  }
  __syncthreads();
  if (tid < 64){
    float s2 = red[tid*2] + red[tid*2+1];
    float nrm = fmaxf(fabsf(s2), g_mexp[bh*2048 + i0 + tid]);
    sinv[tid] = 1.f/(nrm + 1e-6f);
  }
  __syncthreads();

  float iv0 = sinv[qm+gid], iv1 = sinv[qm+gid+8];
  float* obase = g_h + ((size_t)(b*2048 + i0))*512 + h*128;
  #pragma unroll
  for (int nt=0;nt<8;nt++){
    int col = wc*64+nt*8+tig*2;
    *(float2*)&obase[(size_t)(qm+gid)*512 + col] =
      make_float2(oacc[nt][0]*iv0, oacc[nt][1]*iv0);
    *(float2*)&obase[(size_t)(qm+gid+8)*512 + col] =
      make_float2(oacc[nt][2]*iv1, oacc[nt][3]*iv1);
  }
}

// ---------------- groupnorm + skip + z-gate ----------------
__global__ void k_norm(const float* __restrict__ skip){
  int r = blockIdx.x; int t = threadIdx.x;
  float v[4];
  #pragma unroll
  for (int h=0;h<4;h++) v[h] = g_h[(size_t)r*512 + h*128 + t];
  __shared__ float rs[4][128], rq[4][128];
  #pragma unroll
  for (int h=0;h<4;h++){ rs[h][t]=v[h]; rq[h][t]=v[h]*v[h]; }
  __syncthreads();
  for (int sft=64; sft>=1; sft>>=1){
    if (t < sft){
      #pragma unroll
      for (int h=0;h<4;h++){ rs[h][t]+=rs[h][t+sft]; rq[h][t]+=rq[h][t+sft]; }
    }
    __syncthreads();
  }
  #pragma unroll
  for (int h=0;h<4;h++){
    float mean = rs[h][0]*(1.f/128.f);
    float var  = rq[h][0]*(1.f/128.f) - mean*mean;
    float hn = (v[h]-mean)*rsqrtf(var + 1e-5f);
    int e = h*128 + t;
    float hskip = hn + skip[e]*g_xc[(size_t)r*512 + e];
    g_hs[(size_t)r*512 + e] = hskip * g_zsil[(size_t)r*512 + e];
  }
}

// ---------------- launch ----------------
extern "C" void kernel_launch(void* const* d_in, const int* in_sizes, int n_in,
                              void* d_out, int out_size){
  const float* x      = (const float*)d_in[0];
  const float* W_up   = (const float*)d_in[1];
  const float* Wq     = (const float*)d_in[2];
  const float* Wk     = (const float*)d_in[3];
  const float* Wv     = (const float*)d_in[4];
  const float* conv_w = (const float*)d_in[5];
  const float* conv_b = (const float*)d_in[6];
  const float* Wi     = (const float*)d_in[7];
  const float* bi     = (const float*)d_in[8];
  const float* Wf     = (const float*)d_in[9];
  const float* bf     = (const float*)d_in[10];
  const float* skip   = (const float*)d_in[11];
  const float* W_down = (const float*)d_in[12];
  const float* b_down = (const float*)d_in[13];
  float* out = (float*)d_out;

  cudaFuncSetAttribute(k_attn, cudaFuncAttributeMaxDynamicSharedMemorySize, ATT_SMEM);
  cudaFuncSetAttribute(k_up,   cudaFuncAttributeMaxDynamicSharedMemorySize, GEMM_SMEM);
  cudaFuncSetAttribute(k_conv, cudaFuncAttributeMaxDynamicSharedMemorySize, GEMM_SMEM);
  cudaFuncSetAttribute(k_qkv,  cudaFuncAttributeMaxDynamicSharedMemorySize, GEMM_SMEM);
  cudaFuncSetAttribute(k_down, cudaFuncAttributeMaxDynamicSharedMemorySize, GEMM_SMEM);

  k_wt  <<<512, 512>>>(conv_w);
  k_up  <<<dim3(8,32), 256, GEMM_SMEM>>>(x, W_up);
  k_conv<<<dim3(4,32), 256, GEMM_SMEM>>>(conv_b);
  k_qkv <<<dim3(1,32,12), 256, GEMM_SMEM>>>(Wq, Wk, Wv);
  k_gates<<<4096,128>>>(Wi, bi, Wf, bf);
  k_scan<<<8,256>>>();
  k_attn<<<dim3(32,8),256, ATT_SMEM>>>();
  k_norm<<<4096,128>>>(skip);
  k_down<<<dim3(4,32),256, GEMM_SMEM>>>(W_down, b_down, out);
}